// round 6
// baseline (speedup 1.0000x reference)
#include <cuda_runtime.h>
#include <cuda_bf16.h>
#include <cuda_fp16.h>
#include <math_constants.h>
#include <cstdint>

// ---------------------------------------------------------------------------
// MultiheadAttention (T=2048, B=2, E=1024, H=16, D=64) fp32.
// QKV/out projections: 3-pass bf16-split HMMA, pass-major MMA schedule
// (16 independent accumulators between C-register reuse).
// Attention: fp16 HMMA, 1-pass QK^T + 1-pass PV, fp32 softmax.
// ---------------------------------------------------------------------------

#define EMBED   1024
#define NHEAD   16
#define HDIM    64
#define TLEN    2048
#define BSZ     2
#define MROWS   4096
#define QKV_N   3072

// ------------------------------- scratch -----------------------------------
__device__ __nv_bfloat16 g_xhi [(size_t)MROWS * EMBED];
__device__ __nv_bfloat16 g_xlo [(size_t)MROWS * EMBED];
__device__ __nv_bfloat16 g_winhi[(size_t)QKV_N * EMBED];
__device__ __nv_bfloat16 g_winlo[(size_t)QKV_N * EMBED];
__device__ __nv_bfloat16 g_wohi[(size_t)EMBED * EMBED];
__device__ __nv_bfloat16 g_wolo[(size_t)EMBED * EMBED];
__device__ __half        g_qkvh[(size_t)MROWS * QKV_N];
__device__ __nv_bfloat16 g_ahi [(size_t)MROWS * EMBED];
__device__ __nv_bfloat16 g_alo [(size_t)MROWS * EMBED];

// --------------------------- asm helpers -----------------------------------
__device__ __forceinline__ uint32_t smem_u32(const void* p) {
    uint32_t a;
    asm("{ .reg .u64 t; cvta.to.shared.u64 t, %1; cvt.u32.u64 %0, t; }"
        : "=r"(a) : "l"(p));
    return a;
}
__device__ __forceinline__ void ldsm4(uint32_t* r, uint32_t a) {
    asm volatile("ldmatrix.sync.aligned.m8n8.x4.shared.b16 {%0,%1,%2,%3}, [%4];"
        : "=r"(r[0]), "=r"(r[1]), "=r"(r[2]), "=r"(r[3]) : "r"(a));
}
__device__ __forceinline__ void ldsm4t(uint32_t* r, uint32_t a) {
    asm volatile("ldmatrix.sync.aligned.m8n8.x4.trans.shared.b16 {%0,%1,%2,%3}, [%4];"
        : "=r"(r[0]), "=r"(r[1]), "=r"(r[2]), "=r"(r[3]) : "r"(a));
}
__device__ __forceinline__ void mma_bf16(float* c, const uint32_t* a, const uint32_t* b) {
    asm volatile(
        "mma.sync.aligned.m16n8k16.row.col.f32.bf16.bf16.f32 "
        "{%0,%1,%2,%3}, {%4,%5,%6,%7}, {%8,%9}, {%0,%1,%2,%3};"
        : "+f"(c[0]), "+f"(c[1]), "+f"(c[2]), "+f"(c[3])
        : "r"(a[0]), "r"(a[1]), "r"(a[2]), "r"(a[3]), "r"(b[0]), "r"(b[1]));
}
__device__ __forceinline__ void mma_f16(float* c, const uint32_t* a, const uint32_t* b) {
    asm volatile(
        "mma.sync.aligned.m16n8k16.row.col.f32.f16.f16.f32 "
        "{%0,%1,%2,%3}, {%4,%5,%6,%7}, {%8,%9}, {%0,%1,%2,%3};"
        : "+f"(c[0]), "+f"(c[1]), "+f"(c[2]), "+f"(c[3])
        : "r"(a[0]), "r"(a[1]), "r"(a[2]), "r"(a[3]), "r"(b[0]), "r"(b[1]));
}
__device__ __forceinline__ void cpa16(uint32_t dst, const void* src) {
    asm volatile("cp.async.cg.shared.global [%0], [%1], 16;" :: "r"(dst), "l"(src));
}
#define CP_COMMIT() asm volatile("cp.async.commit_group;")
#define CP_WAIT0()  asm volatile("cp.async.wait_group 0;")

__device__ __forceinline__ uint32_t packh(float x, float y) {
    __half2 t = __floats2half2_rn(x, y);
    return *(uint32_t*)&t;
}
__device__ __forceinline__ void store_hilo(
    __nv_bfloat16* hi, __nv_bfloat16* lo, size_t idx, float a, float b)
{
    __nv_bfloat16 h0 = __float2bfloat16(a), h1 = __float2bfloat16(b);
    __nv_bfloat16 l0 = __float2bfloat16(a - __bfloat162float(h0));
    __nv_bfloat16 l1 = __float2bfloat16(b - __bfloat162float(h1));
    *(__nv_bfloat162*)(hi + idx) = __nv_bfloat162(h0, h1);
    *(__nv_bfloat162*)(lo + idx) = __nv_bfloat162(l0, l1);
}

// ---------------------------------------------------------------------------
__global__ void __launch_bounds__(256) split_bf16(
    const float* __restrict__ src, __nv_bfloat16* __restrict__ hi,
    __nv_bfloat16* __restrict__ lo, int n4)
{
    int i = blockIdx.x * 256 + threadIdx.x;
    if (i >= n4) return;
    float4 v = *(const float4*)(src + (size_t)i * 4);
    store_hilo(hi, lo, (size_t)i * 4,     v.x, v.y);
    store_hilo(hi, lo, (size_t)i * 4 + 2, v.z, v.w);
}

// ---------------------------------------------------------------------------
// HMMA GEMM-NT + bias (3-pass bf16 split).  MODE 0: fp32 out. MODE 2: fp16 out.
// 128x128 CTA tile, BK=32, 8 warps, warp tile 64x32, cp.async 2-stage,
// single __syncthreads per K-step.  Pass-major MMA schedule: per k-step, each
// accumulator still receives hh, hl, lh in that order (bit-identical to the
// accumulator-major schedule), but 16 independent MMAs sit between reuses.
// ---------------------------------------------------------------------------
#define GSTRIDE 40
#define GTILEB  (128 * GSTRIDE * 2)   // 10240 B
#define GSTAGE  (4 * GTILEB)          // 40960 B

template<int MODE>
__global__ void __launch_bounds__(256) gemm_mma(
    const __nv_bfloat16* __restrict__ Ahi, const __nv_bfloat16* __restrict__ Alo,
    const __nv_bfloat16* __restrict__ Bhi, const __nv_bfloat16* __restrict__ Blo,
    const float* __restrict__ bias, float* __restrict__ Cf,
    __half* __restrict__ Ch, int N, int K)
{
    extern __shared__ char smem[];
    const uint32_t sbase = smem_u32(smem);
    const int tid = threadIdx.x, wid = tid >> 5, lane = tid & 31;
    const int bm = blockIdx.y, bn = blockIdx.x;
    const int wm = wid >> 2, wn = wid & 3;

    float acc[4][4][4];
#pragma unroll
    for (int a = 0; a < 4; a++)
#pragma unroll
        for (int b = 0; b < 4; b++)
#pragma unroll
            for (int c = 0; c < 4; c++) acc[a][b][c] = 0.0f;

    auto prefetch = [&](int it) {
        const int k0 = it << 5;
        const int buf = it & 1;
#pragma unroll
        for (int i = 0; i < 8; i++) {
            int g = tid + i * 256;
            int t = g >> 9;
            int c = g & 511;
            int row = c >> 2, c16 = c & 3;
            const __nv_bfloat16* P = (t == 0) ? Ahi : (t == 1) ? Alo
                                   : (t == 2) ? Bhi : Blo;
            int rb = (t < 2) ? bm * 128 : bn * 128;
            const void* src = P + (size_t)(rb + row) * K + k0 + c16 * 8;
            uint32_t dst = sbase + buf * GSTAGE + t * GTILEB
                         + (row * GSTRIDE + c16 * 8) * 2;
            cpa16(dst, src);
        }
        CP_COMMIT();
    };

    const int niter = K >> 5;
    prefetch(0);
    for (int it = 0; it < niter; it++) {
        CP_WAIT0();
        __syncthreads();
        if (it + 1 < niter) prefetch(it + 1);

        const uint32_t st   = sbase + (it & 1) * GSTAGE;
        const uint32_t tAhi = st,               tAlo = st + GTILEB;
        const uint32_t tBhi = st + 2 * GTILEB,  tBlo = st + 3 * GTILEB;

        const int ar = lane & 15, ac = (lane >> 4) * 8;
        const int br = (lane & 7) + ((lane & 16) ? 8 : 0);
        const int bc = (lane & 8) ? 8 : 0;

#pragma unroll
        for (int ks = 0; ks < 2; ks++) {
            const int k0 = ks * 16;
            uint32_t ah[4][4], al[4][4], bh[4][2], bl[4][2];
#pragma unroll
            for (int mi = 0; mi < 4; mi++) {
                uint32_t off = ((wm * 64 + mi * 16 + ar) * GSTRIDE + k0 + ac) * 2;
                ldsm4(ah[mi], tAhi + off);
                ldsm4(al[mi], tAlo + off);
            }
#pragma unroll
            for (int p = 0; p < 2; p++) {
                uint32_t off = ((wn * 32 + p * 16 + br) * GSTRIDE + k0 + bc) * 2;
                uint32_t r[4];
                ldsm4(r, tBhi + off);
                bh[2*p][0] = r[0]; bh[2*p][1] = r[1];
                bh[2*p+1][0] = r[2]; bh[2*p+1][1] = r[3];
                ldsm4(r, tBlo + off);
                bl[2*p][0] = r[0]; bl[2*p][1] = r[1];
                bl[2*p+1][0] = r[2]; bl[2*p+1][1] = r[3];
            }
            // pass-major: 16 independent accumulators between reuses
#pragma unroll
            for (int mi = 0; mi < 4; mi++)
#pragma unroll
                for (int ni = 0; ni < 4; ni++)
                    mma_bf16(acc[mi][ni], ah[mi], bh[ni]);
#pragma unroll
            for (int mi = 0; mi < 4; mi++)
#pragma unroll
                for (int ni = 0; ni < 4; ni++)
                    mma_bf16(acc[mi][ni], ah[mi], bl[ni]);
#pragma unroll
            for (int mi = 0; mi < 4; mi++)
#pragma unroll
                for (int ni = 0; ni < 4; ni++)
                    mma_bf16(acc[mi][ni], al[mi], bh[ni]);
        }
    }

    const int r = lane >> 2, q = lane & 3;
#pragma unroll
    for (int mi = 0; mi < 4; mi++) {
#pragma unroll
        for (int ni = 0; ni < 4; ni++) {
            int row = bm * 128 + wm * 64 + mi * 16 + r;
            int col = bn * 128 + wn * 32 + ni * 8 + 2 * q;
            float b0 = bias[col], b1 = bias[col + 1];
            float v0 = acc[mi][ni][0] + b0, v1 = acc[mi][ni][1] + b1;
            float v2 = acc[mi][ni][2] + b0, v3 = acc[mi][ni][3] + b1;
            if (MODE == 0) {
                *(float2*)(Cf + (size_t)row * N + col)       = make_float2(v0, v1);
                *(float2*)(Cf + (size_t)(row + 8) * N + col) = make_float2(v2, v3);
            } else {
                *(__half2*)(Ch + (size_t)row * N + col)       = __floats2half2_rn(v0, v1);
                *(__half2*)(Ch + (size_t)(row + 8) * N + col) = __floats2half2_rn(v2, v3);
            }
        }
    }
}

// ---------------------------------------------------------------------------
// Flash attention, fp16 HMMA. Block = (q-tile 128, b*H+h), 256 threads/8 warps.
// ---------------------------------------------------------------------------
#define AST  72
#define ATBF (64 * AST * 2)     // 9216 B per K/V tile
#define QSTG (128 * AST * 2)    // 18432 B

__global__ void __launch_bounds__(256) attn_f16(
    const __half* __restrict__ qkv,
    __nv_bfloat16* __restrict__ ohi, __nv_bfloat16* __restrict__ olo)
{
    extern __shared__ char smem[];
    const uint32_t sb  = smem_u32(smem);
    const uint32_t sQ  = sb;
    const uint32_t sKV = sb + QSTG;

    const int tid = threadIdx.x, wid = tid >> 5, lane = tid & 31;
    const int qt = blockIdx.x, bh = blockIdx.y, b = bh >> 4, h = bh & 15;

    auto pf = [&](int st) {
        const int buf = st & 1;
#pragma unroll
        for (int i = 0; i < 4; i++) {
            int c  = tid + i * 256;        // 0..1023
            int kv = c >> 9;               // 0=K, 1=V
            int e  = c & 511;
            int row = e >> 3, ch = e & 7;
            const void* src = qkv + ((size_t)((st * 64 + row) * 2 + b)) * QKV_N
                            + (kv ? 2 * EMBED : EMBED) + h * 64 + ch * 8;
            uint32_t dst = sKV + (buf * 2 + kv) * ATBF + (row * AST + ch * 8) * 2;
            cpa16(dst, src);
        }
        CP_COMMIT();
    };

    pf(0);

    const __half2 s2 = __floats2half2_rn(0.125f, 0.125f);
#pragma unroll
    for (int i = 0; i < 4; i++) {
        int c = tid + i * 256;
        int row = c >> 3, ch = c & 7;
        int t = qt * 128 + row;
        uint4 v = *(const uint4*)(qkv + ((size_t)(t * 2 + b)) * QKV_N + h * 64 + ch * 8);
        __half2* p = (__half2*)&v;
#pragma unroll
        for (int j = 0; j < 4; j++) p[j] = __hmul2(p[j], s2);
        *(uint4*)(smem + (row * AST + ch * 8) * 2) = v;
    }
    __syncthreads();

    uint32_t qf[4][4];
    {
        const int ar = lane & 15, ac = (lane >> 4) * 8;
#pragma unroll
        for (int kt = 0; kt < 4; kt++)
            ldsm4(qf[kt], sQ + ((wid * 16 + ar) * AST + kt * 16 + ac) * 2);
    }

    float O[8][4];
#pragma unroll
    for (int i = 0; i < 8; i++)
#pragma unroll
        for (int j = 0; j < 4; j++) O[i][j] = 0.0f;
    float m0 = -CUDART_INF_F, m1 = -CUDART_INF_F, l0 = 0.0f, l1 = 0.0f;

    const int br = (lane & 7) + ((lane & 16) ? 8 : 0);
    const int bc = (lane & 8) ? 8 : 0;
    const int vr = lane & 15, vc = (lane >> 4) * 8;

    for (int st = 0; st < TLEN / 64; st++) {
        CP_WAIT0();
        __syncthreads();
        if (st + 1 < TLEN / 64) pf(st + 1);

        const uint32_t sK = sKV + ((st & 1) * 2) * ATBF;
        const uint32_t sV = sK + ATBF;

        float s4[8][4];
#pragma unroll
        for (int i = 0; i < 8; i++)
#pragma unroll
            for (int j = 0; j < 4; j++) s4[i][j] = 0.0f;

#pragma unroll
        for (int kt = 0; kt < 4; kt++) {
            uint32_t kh[8][2];
#pragma unroll
            for (int p = 0; p < 4; p++) {
                uint32_t r[4];
                ldsm4(r, sK + ((p * 16 + br) * AST + kt * 16 + bc) * 2);
                kh[2*p][0] = r[0]; kh[2*p][1] = r[1];
                kh[2*p+1][0] = r[2]; kh[2*p+1][1] = r[3];
            }
#pragma unroll
            for (int nt = 0; nt < 8; nt++)
                mma_f16(s4[nt], qf[kt], kh[nt]);
        }

        float mx0 = -CUDART_INF_F, mx1 = -CUDART_INF_F;
#pragma unroll
        for (int nt = 0; nt < 8; nt++) {
            mx0 = fmaxf(mx0, fmaxf(s4[nt][0], s4[nt][1]));
            mx1 = fmaxf(mx1, fmaxf(s4[nt][2], s4[nt][3]));
        }
        mx0 = fmaxf(mx0, __shfl_xor_sync(0xffffffffu, mx0, 1));
        mx0 = fmaxf(mx0, __shfl_xor_sync(0xffffffffu, mx0, 2));
        mx1 = fmaxf(mx1, __shfl_xor_sync(0xffffffffu, mx1, 1));
        mx1 = fmaxf(mx1, __shfl_xor_sync(0xffffffffu, mx1, 2));

        float mn0 = fmaxf(m0, mx0), mn1 = fmaxf(m1, mx1);
        float a0 = __expf(m0 - mn0), a1 = __expf(m1 - mn1);
        m0 = mn0; m1 = mn1;

        uint32_t pa[4][4];
        float sum0 = 0.0f, sum1 = 0.0f;
#pragma unroll
        for (int jj = 0; jj < 4; jj++) {
            float p00 = __expf(s4[2*jj][0]   - mn0), p01 = __expf(s4[2*jj][1]   - mn0);
            float p02 = __expf(s4[2*jj][2]   - mn1), p03 = __expf(s4[2*jj][3]   - mn1);
            float p10 = __expf(s4[2*jj+1][0] - mn0), p11 = __expf(s4[2*jj+1][1] - mn0);
            float p12 = __expf(s4[2*jj+1][2] - mn1), p13 = __expf(s4[2*jj+1][3] - mn1);
            pa[jj][0] = packh(p00, p01);
            pa[jj][1] = packh(p02, p03);
            pa[jj][2] = packh(p10, p11);
            pa[jj][3] = packh(p12, p13);
            float2 f;
            f = __half22float2(*(__half2*)&pa[jj][0]); sum0 += f.x + f.y;
            f = __half22float2(*(__half2*)&pa[jj][2]); sum0 += f.x + f.y;
            f = __half22float2(*(__half2*)&pa[jj][1]); sum1 += f.x + f.y;
            f = __half22float2(*(__half2*)&pa[jj][3]); sum1 += f.x + f.y;
        }
        sum0 += __shfl_xor_sync(0xffffffffu, sum0, 1);
        sum0 += __shfl_xor_sync(0xffffffffu, sum0, 2);
        sum1 += __shfl_xor_sync(0xffffffffu, sum1, 1);
        sum1 += __shfl_xor_sync(0xffffffffu, sum1, 2);
        l0 = l0 * a0 + sum0;
        l1 = l1 * a1 + sum1;
#pragma unroll
        for (int nt = 0; nt < 8; nt++) {
            O[nt][0] *= a0; O[nt][1] *= a0; O[nt][2] *= a1; O[nt][3] *= a1;
        }

#pragma unroll
        for (int kt = 0; kt < 4; kt++) {
#pragma unroll
            for (int p = 0; p < 4; p++) {
                uint32_t r[4];
                ldsm4t(r, sV + ((kt * 16 + vr) * AST + p * 16 + vc) * 2);
                mma_f16(O[2*p],   pa[kt], r);
                mma_f16(O[2*p+1], pa[kt], r + 2);
            }
        }
    }

    const float inv0 = 1.0f / l0, inv1 = 1.0f / l1;
    const int r = lane >> 2, q = lane & 3;
    const int t0 = qt * 128 + wid * 16 + r;
#pragma unroll
    for (int nt = 0; nt < 8; nt++) {
        int d = nt * 8 + 2 * q;
        size_t i0 = ((size_t)(t0 * 2 + b)) * EMBED + h * 64 + d;
        size_t i1 = ((size_t)((t0 + 8) * 2 + b)) * EMBED + h * 64 + d;
        store_hilo(ohi, olo, i0, O[nt][0] * inv0, O[nt][1] * inv0);
        store_hilo(ohi, olo, i1, O[nt][2] * inv1, O[nt][3] * inv1);
    }
}

// ---------------------------------------------------------------------------
extern "C" void kernel_launch(void* const* d_in, const int* in_sizes, int n_in,
                              void* d_out, int out_size)
{
    const float* x     = (const float*)d_in[0];
    const float* w_in  = (const float*)d_in[1];
    const float* b_in  = (const float*)d_in[2];
    const float* w_out = (const float*)d_in[3];
    const float* b_out = (const float*)d_in[4];
    float* out = (float*)d_out;

    void *xhi, *xlo, *winhi, *winlo, *wohi, *wolo, *qkvh, *ahi, *alo;
    cudaGetSymbolAddress(&xhi, g_xhi);     cudaGetSymbolAddress(&xlo, g_xlo);
    cudaGetSymbolAddress(&winhi, g_winhi); cudaGetSymbolAddress(&winlo, g_winlo);
    cudaGetSymbolAddress(&wohi, g_wohi);   cudaGetSymbolAddress(&wolo, g_wolo);
    cudaGetSymbolAddress(&qkvh, g_qkvh);
    cudaGetSymbolAddress(&ahi, g_ahi);     cudaGetSymbolAddress(&alo, g_alo);

    const int gemm_smem = 2 * GSTAGE;                 // 81920
    const int attn_smem = QSTG + 4 * ATBF;            // 55296
    cudaFuncSetAttribute(gemm_mma<0>,
        cudaFuncAttributeMaxDynamicSharedMemorySize, gemm_smem);
    cudaFuncSetAttribute(gemm_mma<2>,
        cudaFuncAttributeMaxDynamicSharedMemorySize, gemm_smem);
    cudaFuncSetAttribute(attn_f16,
        cudaFuncAttributeMaxDynamicSharedMemorySize, attn_smem);

    int n4 = MROWS * EMBED / 4;
    split_bf16<<<(n4 + 255) / 256, 256>>>(x, (__nv_bfloat16*)xhi,
                                          (__nv_bfloat16*)xlo, n4);
    n4 = QKV_N * EMBED / 4;
    split_bf16<<<(n4 + 255) / 256, 256>>>(w_in, (__nv_bfloat16*)winhi,
                                          (__nv_bfloat16*)winlo, n4);
    n4 = EMBED * EMBED / 4;
    split_bf16<<<(n4 + 255) / 256, 256>>>(w_out, (__nv_bfloat16*)wohi,
                                          (__nv_bfloat16*)wolo, n4);

    // 1) QKV projection -> fp16 qkv
    gemm_mma<2><<<dim3(QKV_N / 128, MROWS / 128), 256, gemm_smem>>>(
        (const __nv_bfloat16*)xhi, (const __nv_bfloat16*)xlo,
        (const __nv_bfloat16*)winhi, (const __nv_bfloat16*)winlo,
        b_in, nullptr, (__half*)qkvh, QKV_N, EMBED);

    // 2) attention -> bf16 hi/lo
    attn_f16<<<dim3(TLEN / 128, BSZ * NHEAD), 256, attn_smem>>>(
        (const __half*)qkvh, (__nv_bfloat16*)ahi, (__nv_bfloat16*)alo);

    // 3) output projection -> fp32 out
    gemm_mma<0><<<dim3(EMBED / 128, MROWS / 128), 256, gemm_smem>>>(
        (const __nv_bfloat16*)ahi, (const __nv_bfloat16*)alo,
        (const __nv_bfloat16*)wohi, (const __nv_bfloat16*)wolo,
        b_out, out, nullptr, EMBED, EMBED);
}

// round 7
// speedup vs baseline: 1.0388x; 1.0388x over previous
#include <cuda_runtime.h>
#include <cuda_bf16.h>
#include <cuda_fp16.h>
#include <math_constants.h>
#include <cstdint>

// ---------------------------------------------------------------------------
// MultiheadAttention (T=2048, B=2, E=1024, H=16, D=64) fp32.
// QKV/out projections: 3-pass bf16-split HMMA, 4 warps x (64x64) warp tiles.
// Attention: fp16 HMMA, 1-pass QK^T + 1-pass PV, fp32 softmax.
// ---------------------------------------------------------------------------

#define EMBED   1024
#define NHEAD   16
#define HDIM    64
#define TLEN    2048
#define BSZ     2
#define MROWS   4096
#define QKV_N   3072

// ------------------------------- scratch -----------------------------------
__device__ __nv_bfloat16 g_xhi [(size_t)MROWS * EMBED];
__device__ __nv_bfloat16 g_xlo [(size_t)MROWS * EMBED];
__device__ __nv_bfloat16 g_winhi[(size_t)QKV_N * EMBED];
__device__ __nv_bfloat16 g_winlo[(size_t)QKV_N * EMBED];
__device__ __nv_bfloat16 g_wohi[(size_t)EMBED * EMBED];
__device__ __nv_bfloat16 g_wolo[(size_t)EMBED * EMBED];
__device__ __half        g_qkvh[(size_t)MROWS * QKV_N];
__device__ __nv_bfloat16 g_ahi [(size_t)MROWS * EMBED];
__device__ __nv_bfloat16 g_alo [(size_t)MROWS * EMBED];

// --------------------------- asm helpers -----------------------------------
__device__ __forceinline__ uint32_t smem_u32(const void* p) {
    uint32_t a;
    asm("{ .reg .u64 t; cvta.to.shared.u64 t, %1; cvt.u32.u64 %0, t; }"
        : "=r"(a) : "l"(p));
    return a;
}
__device__ __forceinline__ void ldsm4(uint32_t* r, uint32_t a) {
    asm volatile("ldmatrix.sync.aligned.m8n8.x4.shared.b16 {%0,%1,%2,%3}, [%4];"
        : "=r"(r[0]), "=r"(r[1]), "=r"(r[2]), "=r"(r[3]) : "r"(a));
}
__device__ __forceinline__ void ldsm4t(uint32_t* r, uint32_t a) {
    asm volatile("ldmatrix.sync.aligned.m8n8.x4.trans.shared.b16 {%0,%1,%2,%3}, [%4];"
        : "=r"(r[0]), "=r"(r[1]), "=r"(r[2]), "=r"(r[3]) : "r"(a));
}
__device__ __forceinline__ void mma_bf16(float* c, const uint32_t* a, const uint32_t* b) {
    asm volatile(
        "mma.sync.aligned.m16n8k16.row.col.f32.bf16.bf16.f32 "
        "{%0,%1,%2,%3}, {%4,%5,%6,%7}, {%8,%9}, {%0,%1,%2,%3};"
        : "+f"(c[0]), "+f"(c[1]), "+f"(c[2]), "+f"(c[3])
        : "r"(a[0]), "r"(a[1]), "r"(a[2]), "r"(a[3]), "r"(b[0]), "r"(b[1]));
}
__device__ __forceinline__ void mma_f16(float* c, const uint32_t* a, const uint32_t* b) {
    asm volatile(
        "mma.sync.aligned.m16n8k16.row.col.f32.f16.f16.f32 "
        "{%0,%1,%2,%3}, {%4,%5,%6,%7}, {%8,%9}, {%0,%1,%2,%3};"
        : "+f"(c[0]), "+f"(c[1]), "+f"(c[2]), "+f"(c[3])
        : "r"(a[0]), "r"(a[1]), "r"(a[2]), "r"(a[3]), "r"(b[0]), "r"(b[1]));
}
__device__ __forceinline__ void cpa16(uint32_t dst, const void* src) {
    asm volatile("cp.async.cg.shared.global [%0], [%1], 16;" :: "r"(dst), "l"(src));
}
#define CP_COMMIT() asm volatile("cp.async.commit_group;")
#define CP_WAIT0()  asm volatile("cp.async.wait_group 0;")

__device__ __forceinline__ uint32_t packh(float x, float y) {
    __half2 t = __floats2half2_rn(x, y);
    return *(uint32_t*)&t;
}
__device__ __forceinline__ void store_hilo(
    __nv_bfloat16* hi, __nv_bfloat16* lo, size_t idx, float a, float b)
{
    __nv_bfloat16 h0 = __float2bfloat16(a), h1 = __float2bfloat16(b);
    __nv_bfloat16 l0 = __float2bfloat16(a - __bfloat162float(h0));
    __nv_bfloat16 l1 = __float2bfloat16(b - __bfloat162float(h1));
    *(__nv_bfloat162*)(hi + idx) = __nv_bfloat162(h0, h1);
    *(__nv_bfloat162*)(lo + idx) = __nv_bfloat162(l0, l1);
}

// ---------------------------------------------------------------------------
__global__ void __launch_bounds__(256) split_bf16(
    const float* __restrict__ src, __nv_bfloat16* __restrict__ hi,
    __nv_bfloat16* __restrict__ lo, int n4)
{
    int i = blockIdx.x * 256 + threadIdx.x;
    if (i >= n4) return;
    float4 v = *(const float4*)(src + (size_t)i * 4);
    store_hilo(hi, lo, (size_t)i * 4,     v.x, v.y);
    store_hilo(hi, lo, (size_t)i * 4 + 2, v.z, v.w);
}

// ---------------------------------------------------------------------------
// HMMA GEMM-NT + bias (3-pass bf16 split).  MODE 0: fp32 out. MODE 2: fp16 out.
// 128x128 CTA tile, BK=32, 4 warps (2x2), warp tile 64x64, cp.async 2-stage,
// single __syncthreads per K-step. 6 MMAs per ldmatrix.x4.
// ---------------------------------------------------------------------------
#define GSTRIDE 40
#define GTILEB  (128 * GSTRIDE * 2)   // 10240 B
#define GSTAGE  (4 * GTILEB)          // 40960 B

template<int MODE>
__global__ void __launch_bounds__(128, 2) gemm_mma(
    const __nv_bfloat16* __restrict__ Ahi, const __nv_bfloat16* __restrict__ Alo,
    const __nv_bfloat16* __restrict__ Bhi, const __nv_bfloat16* __restrict__ Blo,
    const float* __restrict__ bias, float* __restrict__ Cf,
    __half* __restrict__ Ch, int N, int K)
{
    extern __shared__ char smem[];
    const uint32_t sbase = smem_u32(smem);
    const int tid = threadIdx.x, wid = tid >> 5, lane = tid & 31;
    const int bm = blockIdx.y, bn = blockIdx.x;
    const int wm = wid >> 1, wn = wid & 1;      // 2x2 warp grid, 64x64 tiles

    float acc[4][8][4];
#pragma unroll
    for (int a = 0; a < 4; a++)
#pragma unroll
        for (int b = 0; b < 8; b++)
#pragma unroll
            for (int c = 0; c < 4; c++) acc[a][b][c] = 0.0f;

    // 4 tensors x 128 rows x 32 cols bf16 = 2048 x 16B transfers, 16/thread.
    auto prefetch = [&](int it) {
        const int k0 = it << 5;
        const int buf = it & 1;
#pragma unroll
        for (int i = 0; i < 16; i++) {
            int g = tid + i * 128;            // 0..2047
            int t = g >> 9;                   // tensor 0..3 (uniform per i)
            int c = g & 511;
            int row = c >> 2, c16 = c & 3;
            const __nv_bfloat16* P = (t == 0) ? Ahi : (t == 1) ? Alo
                                   : (t == 2) ? Bhi : Blo;
            int rb = (t < 2) ? bm * 128 : bn * 128;
            const void* src = P + (size_t)(rb + row) * K + k0 + c16 * 8;
            uint32_t dst = sbase + buf * GSTAGE + t * GTILEB
                         + (row * GSTRIDE + c16 * 8) * 2;
            cpa16(dst, src);
        }
        CP_COMMIT();
    };

    const int niter = K >> 5;
    prefetch(0);
    for (int it = 0; it < niter; it++) {
        CP_WAIT0();
        __syncthreads();
        if (it + 1 < niter) prefetch(it + 1);

        const uint32_t st   = sbase + (it & 1) * GSTAGE;
        const uint32_t tAhi = st,               tAlo = st + GTILEB;
        const uint32_t tBhi = st + 2 * GTILEB,  tBlo = st + 3 * GTILEB;

        const int ar = lane & 15, ac = (lane >> 4) * 8;
        const int br = (lane & 7) + ((lane & 16) ? 8 : 0);
        const int bc = (lane & 8) ? 8 : 0;

#pragma unroll
        for (int ks = 0; ks < 2; ks++) {
            const int k0 = ks * 16;
            uint32_t ah[4][4], al[4][4], bh[8][2], bl[8][2];
#pragma unroll
            for (int mi = 0; mi < 4; mi++) {
                uint32_t off = ((wm * 64 + mi * 16 + ar) * GSTRIDE + k0 + ac) * 2;
                ldsm4(ah[mi], tAhi + off);
                ldsm4(al[mi], tAlo + off);
            }
#pragma unroll
            for (int p = 0; p < 4; p++) {
                uint32_t off = ((wn * 64 + p * 16 + br) * GSTRIDE + k0 + bc) * 2;
                uint32_t r[4];
                ldsm4(r, tBhi + off);
                bh[2*p][0] = r[0]; bh[2*p][1] = r[1];
                bh[2*p+1][0] = r[2]; bh[2*p+1][1] = r[3];
                ldsm4(r, tBlo + off);
                bl[2*p][0] = r[0]; bl[2*p][1] = r[1];
                bl[2*p+1][0] = r[2]; bl[2*p+1][1] = r[3];
            }
#pragma unroll
            for (int mi = 0; mi < 4; mi++)
#pragma unroll
                for (int ni = 0; ni < 8; ni++)
                    mma_bf16(acc[mi][ni], ah[mi], bh[ni]);
#pragma unroll
            for (int mi = 0; mi < 4; mi++)
#pragma unroll
                for (int ni = 0; ni < 8; ni++)
                    mma_bf16(acc[mi][ni], ah[mi], bl[ni]);
#pragma unroll
            for (int mi = 0; mi < 4; mi++)
#pragma unroll
                for (int ni = 0; ni < 8; ni++)
                    mma_bf16(acc[mi][ni], al[mi], bh[ni]);
        }
    }

    const int r = lane >> 2, q = lane & 3;
#pragma unroll
    for (int mi = 0; mi < 4; mi++) {
#pragma unroll
        for (int ni = 0; ni < 8; ni++) {
            int row = bm * 128 + wm * 64 + mi * 16 + r;
            int col = bn * 128 + wn * 64 + ni * 8 + 2 * q;
            float b0 = bias[col], b1 = bias[col + 1];
            float v0 = acc[mi][ni][0] + b0, v1 = acc[mi][ni][1] + b1;
            float v2 = acc[mi][ni][2] + b0, v3 = acc[mi][ni][3] + b1;
            if (MODE == 0) {
                *(float2*)(Cf + (size_t)row * N + col)       = make_float2(v0, v1);
                *(float2*)(Cf + (size_t)(row + 8) * N + col) = make_float2(v2, v3);
            } else {
                *(__half2*)(Ch + (size_t)row * N + col)       = __floats2half2_rn(v0, v1);
                *(__half2*)(Ch + (size_t)(row + 8) * N + col) = __floats2half2_rn(v2, v3);
            }
        }
    }
}

// ---------------------------------------------------------------------------
// Flash attention, fp16 HMMA. Block = (q-tile 128, b*H+h), 256 threads/8 warps.
// ---------------------------------------------------------------------------
#define AST  72
#define ATBF (64 * AST * 2)     // 9216 B per K/V tile
#define QSTG (128 * AST * 2)    // 18432 B

__global__ void __launch_bounds__(256) attn_f16(
    const __half* __restrict__ qkv,
    __nv_bfloat16* __restrict__ ohi, __nv_bfloat16* __restrict__ olo)
{
    extern __shared__ char smem[];
    const uint32_t sb  = smem_u32(smem);
    const uint32_t sQ  = sb;
    const uint32_t sKV = sb + QSTG;

    const int tid = threadIdx.x, wid = tid >> 5, lane = tid & 31;
    const int qt = blockIdx.x, bh = blockIdx.y, b = bh >> 4, h = bh & 15;

    auto pf = [&](int st) {
        const int buf = st & 1;
#pragma unroll
        for (int i = 0; i < 4; i++) {
            int c  = tid + i * 256;        // 0..1023
            int kv = c >> 9;               // 0=K, 1=V
            int e  = c & 511;
            int row = e >> 3, ch = e & 7;
            const void* src = qkv + ((size_t)((st * 64 + row) * 2 + b)) * QKV_N
                            + (kv ? 2 * EMBED : EMBED) + h * 64 + ch * 8;
            uint32_t dst = sKV + (buf * 2 + kv) * ATBF + (row * AST + ch * 8) * 2;
            cpa16(dst, src);
        }
        CP_COMMIT();
    };

    pf(0);

    const __half2 s2 = __floats2half2_rn(0.125f, 0.125f);
#pragma unroll
    for (int i = 0; i < 4; i++) {
        int c = tid + i * 256;
        int row = c >> 3, ch = c & 7;
        int t = qt * 128 + row;
        uint4 v = *(const uint4*)(qkv + ((size_t)(t * 2 + b)) * QKV_N + h * 64 + ch * 8);
        __half2* p = (__half2*)&v;
#pragma unroll
        for (int j = 0; j < 4; j++) p[j] = __hmul2(p[j], s2);
        *(uint4*)(smem + (row * AST + ch * 8) * 2) = v;
    }
    __syncthreads();

    uint32_t qf[4][4];
    {
        const int ar = lane & 15, ac = (lane >> 4) * 8;
#pragma unroll
        for (int kt = 0; kt < 4; kt++)
            ldsm4(qf[kt], sQ + ((wid * 16 + ar) * AST + kt * 16 + ac) * 2);
    }

    float O[8][4];
#pragma unroll
    for (int i = 0; i < 8; i++)
#pragma unroll
        for (int j = 0; j < 4; j++) O[i][j] = 0.0f;
    float m0 = -CUDART_INF_F, m1 = -CUDART_INF_F, l0 = 0.0f, l1 = 0.0f;

    const int br = (lane & 7) + ((lane & 16) ? 8 : 0);
    const int bc = (lane & 8) ? 8 : 0;
    const int vr = lane & 15, vc = (lane >> 4) * 8;

    for (int st = 0; st < TLEN / 64; st++) {
        CP_WAIT0();
        __syncthreads();
        if (st + 1 < TLEN / 64) pf(st + 1);

        const uint32_t sK = sKV + ((st & 1) * 2) * ATBF;
        const uint32_t sV = sK + ATBF;

        float s4[8][4];
#pragma unroll
        for (int i = 0; i < 8; i++)
#pragma unroll
            for (int j = 0; j < 4; j++) s4[i][j] = 0.0f;

#pragma unroll
        for (int kt = 0; kt < 4; kt++) {
            uint32_t kh[8][2];
#pragma unroll
            for (int p = 0; p < 4; p++) {
                uint32_t r[4];
                ldsm4(r, sK + ((p * 16 + br) * AST + kt * 16 + bc) * 2);
                kh[2*p][0] = r[0]; kh[2*p][1] = r[1];
                kh[2*p+1][0] = r[2]; kh[2*p+1][1] = r[3];
            }
#pragma unroll
            for (int nt = 0; nt < 8; nt++)
                mma_f16(s4[nt], qf[kt], kh[nt]);
        }

        float mx0 = -CUDART_INF_F, mx1 = -CUDART_INF_F;
#pragma unroll
        for (int nt = 0; nt < 8; nt++) {
            mx0 = fmaxf(mx0, fmaxf(s4[nt][0], s4[nt][1]));
            mx1 = fmaxf(mx1, fmaxf(s4[nt][2], s4[nt][3]));
        }
        mx0 = fmaxf(mx0, __shfl_xor_sync(0xffffffffu, mx0, 1));
        mx0 = fmaxf(mx0, __shfl_xor_sync(0xffffffffu, mx0, 2));
        mx1 = fmaxf(mx1, __shfl_xor_sync(0xffffffffu, mx1, 1));
        mx1 = fmaxf(mx1, __shfl_xor_sync(0xffffffffu, mx1, 2));

        float mn0 = fmaxf(m0, mx0), mn1 = fmaxf(m1, mx1);
        float a0 = __expf(m0 - mn0), a1 = __expf(m1 - mn1);
        m0 = mn0; m1 = mn1;

        uint32_t pa[4][4];
        float sum0 = 0.0f, sum1 = 0.0f;
#pragma unroll
        for (int jj = 0; jj < 4; jj++) {
            float p00 = __expf(s4[2*jj][0]   - mn0), p01 = __expf(s4[2*jj][1]   - mn0);
            float p02 = __expf(s4[2*jj][2]   - mn1), p03 = __expf(s4[2*jj][3]   - mn1);
            float p10 = __expf(s4[2*jj+1][0] - mn0), p11 = __expf(s4[2*jj+1][1] - mn0);
            float p12 = __expf(s4[2*jj+1][2] - mn1), p13 = __expf(s4[2*jj+1][3] - mn1);
            pa[jj][0] = packh(p00, p01);
            pa[jj][1] = packh(p02, p03);
            pa[jj][2] = packh(p10, p11);
            pa[jj][3] = packh(p12, p13);
            float2 f;
            f = __half22float2(*(__half2*)&pa[jj][0]); sum0 += f.x + f.y;
            f = __half22float2(*(__half2*)&pa[jj][2]); sum0 += f.x + f.y;
            f = __half22float2(*(__half2*)&pa[jj][1]); sum1 += f.x + f.y;
            f = __half22float2(*(__half2*)&pa[jj][3]); sum1 += f.x + f.y;
        }
        sum0 += __shfl_xor_sync(0xffffffffu, sum0, 1);
        sum0 += __shfl_xor_sync(0xffffffffu, sum0, 2);
        sum1 += __shfl_xor_sync(0xffffffffu, sum1, 1);
        sum1 += __shfl_xor_sync(0xffffffffu, sum1, 2);
        l0 = l0 * a0 + sum0;
        l1 = l1 * a1 + sum1;
#pragma unroll
        for (int nt = 0; nt < 8; nt++) {
            O[nt][0] *= a0; O[nt][1] *= a0; O[nt][2] *= a1; O[nt][3] *= a1;
        }

#pragma unroll
        for (int kt = 0; kt < 4; kt++) {
#pragma unroll
            for (int p = 0; p < 4; p++) {
                uint32_t r[4];
                ldsm4t(r, sV + ((kt * 16 + vr) * AST + p * 16 + vc) * 2);
                mma_f16(O[2*p],   pa[kt], r);
                mma_f16(O[2*p+1], pa[kt], r + 2);
            }
        }
    }

    const float inv0 = 1.0f / l0, inv1 = 1.0f / l1;
    const int r = lane >> 2, q = lane & 3;
    const int t0 = qt * 128 + wid * 16 + r;
#pragma unroll
    for (int nt = 0; nt < 8; nt++) {
        int d = nt * 8 + 2 * q;
        size_t i0 = ((size_t)(t0 * 2 + b)) * EMBED + h * 64 + d;
        size_t i1 = ((size_t)((t0 + 8) * 2 + b)) * EMBED + h * 64 + d;
        store_hilo(ohi, olo, i0, O[nt][0] * inv0, O[nt][1] * inv0);
        store_hilo(ohi, olo, i1, O[nt][2] * inv1, O[nt][3] * inv1);
    }
}

// ---------------------------------------------------------------------------
extern "C" void kernel_launch(void* const* d_in, const int* in_sizes, int n_in,
                              void* d_out, int out_size)
{
    const float* x     = (const float*)d_in[0];
    const float* w_in  = (const float*)d_in[1];
    const float* b_in  = (const float*)d_in[2];
    const float* w_out = (const float*)d_in[3];
    const float* b_out = (const float*)d_in[4];
    float* out = (float*)d_out;

    void *xhi, *xlo, *winhi, *winlo, *wohi, *wolo, *qkvh, *ahi, *alo;
    cudaGetSymbolAddress(&xhi, g_xhi);     cudaGetSymbolAddress(&xlo, g_xlo);
    cudaGetSymbolAddress(&winhi, g_winhi); cudaGetSymbolAddress(&winlo, g_winlo);
    cudaGetSymbolAddress(&wohi, g_wohi);   cudaGetSymbolAddress(&wolo, g_wolo);
    cudaGetSymbolAddress(&qkvh, g_qkvh);
    cudaGetSymbolAddress(&ahi, g_ahi);     cudaGetSymbolAddress(&alo, g_alo);

    const int gemm_smem = 2 * GSTAGE;                 // 81920
    const int attn_smem = QSTG + 4 * ATBF;            // 55296
    cudaFuncSetAttribute(gemm_mma<0>,
        cudaFuncAttributeMaxDynamicSharedMemorySize, gemm_smem);
    cudaFuncSetAttribute(gemm_mma<2>,
        cudaFuncAttributeMaxDynamicSharedMemorySize, gemm_smem);
    cudaFuncSetAttribute(attn_f16,
        cudaFuncAttributeMaxDynamicSharedMemorySize, attn_smem);

    int n4 = MROWS * EMBED / 4;
    split_bf16<<<(n4 + 255) / 256, 256>>>(x, (__nv_bfloat16*)xhi,
                                          (__nv_bfloat16*)xlo, n4);
    n4 = QKV_N * EMBED / 4;
    split_bf16<<<(n4 + 255) / 256, 256>>>(w_in, (__nv_bfloat16*)winhi,
                                          (__nv_bfloat16*)winlo, n4);
    n4 = EMBED * EMBED / 4;
    split_bf16<<<(n4 + 255) / 256, 256>>>(w_out, (__nv_bfloat16*)wohi,
                                          (__nv_bfloat16*)wolo, n4);

    // 1) QKV projection -> fp16 qkv
    gemm_mma<2><<<dim3(QKV_N / 128, MROWS / 128), 128, gemm_smem>>>(
        (const __nv_bfloat16*)xhi, (const __nv_bfloat16*)xlo,
        (const __nv_bfloat16*)winhi, (const __nv_bfloat16*)winlo,
        b_in, nullptr, (__half*)qkvh, QKV_N, EMBED);

    // 2) attention -> bf16 hi/lo
    attn_f16<<<dim3(TLEN / 128, BSZ * NHEAD), 256, attn_smem>>>(
        (const __half*)qkvh, (__nv_bfloat16*)ahi, (__nv_bfloat16*)alo);

    // 3) output projection -> fp32 out
    gemm_mma<0><<<dim3(EMBED / 128, MROWS / 128), 128, gemm_smem>>>(
        (const __nv_bfloat16*)ahi, (const __nv_bfloat16*)alo,
        (const __nv_bfloat16*)wohi, (const __nv_bfloat16*)wolo,
        b_out, out, nullptr, EMBED, EMBED);
}

// round 8
// speedup vs baseline: 1.7591x; 1.6934x over previous
#include <cuda_runtime.h>
#include <cuda_fp16.h>
#include <math_constants.h>
#include <cstdint>

// ---------------------------------------------------------------------------
// MultiheadAttention (T=2048, B=2, E=1024, H=16, D=64) fp32, all-fp16 HMMA:
//   convert x,W to fp16 -> qkv GEMM (1-pass) -> flash attn (fp16) ->
//   out GEMM (1-pass, fp32 epilogue)
// ---------------------------------------------------------------------------

#define EMBED   1024
#define NHEAD   16
#define HDIM    64
#define TLEN    2048
#define BSZ     2
#define MROWS   4096
#define QKV_N   3072

// ------------------------------- scratch -----------------------------------
__device__ __half g_xh  [(size_t)MROWS * EMBED];
__device__ __half g_winh[(size_t)QKV_N * EMBED];
__device__ __half g_woh [(size_t)EMBED * EMBED];
__device__ __half g_qkvh[(size_t)MROWS * QKV_N];
__device__ __half g_ah  [(size_t)MROWS * EMBED];

// --------------------------- asm helpers -----------------------------------
__device__ __forceinline__ uint32_t smem_u32(const void* p) {
    uint32_t a;
    asm("{ .reg .u64 t; cvta.to.shared.u64 t, %1; cvt.u32.u64 %0, t; }"
        : "=r"(a) : "l"(p));
    return a;
}
__device__ __forceinline__ void ldsm4(uint32_t* r, uint32_t a) {
    asm volatile("ldmatrix.sync.aligned.m8n8.x4.shared.b16 {%0,%1,%2,%3}, [%4];"
        : "=r"(r[0]), "=r"(r[1]), "=r"(r[2]), "=r"(r[3]) : "r"(a));
}
__device__ __forceinline__ void ldsm4t(uint32_t* r, uint32_t a) {
    asm volatile("ldmatrix.sync.aligned.m8n8.x4.trans.shared.b16 {%0,%1,%2,%3}, [%4];"
        : "=r"(r[0]), "=r"(r[1]), "=r"(r[2]), "=r"(r[3]) : "r"(a));
}
__device__ __forceinline__ void mma_f16(float* c, const uint32_t* a, const uint32_t* b) {
    asm volatile(
        "mma.sync.aligned.m16n8k16.row.col.f32.f16.f16.f32 "
        "{%0,%1,%2,%3}, {%4,%5,%6,%7}, {%8,%9}, {%0,%1,%2,%3};"
        : "+f"(c[0]), "+f"(c[1]), "+f"(c[2]), "+f"(c[3])
        : "r"(a[0]), "r"(a[1]), "r"(a[2]), "r"(a[3]), "r"(b[0]), "r"(b[1]));
}
__device__ __forceinline__ void cpa16(uint32_t dst, const void* src) {
    asm volatile("cp.async.cg.shared.global [%0], [%1], 16;" :: "r"(dst), "l"(src));
}
#define CP_COMMIT() asm volatile("cp.async.commit_group;")
#define CP_WAIT0()  asm volatile("cp.async.wait_group 0;")

__device__ __forceinline__ uint32_t packh(float x, float y) {
    __half2 t = __floats2half2_rn(x, y);
    return *(uint32_t*)&t;
}

// ---------------------------------------------------------------------------
__global__ void __launch_bounds__(256) conv_f16(
    const float* __restrict__ src, __half* __restrict__ dst, int n8)
{
    int i = blockIdx.x * 256 + threadIdx.x;
    if (i >= n8) return;
    float4 a = *(const float4*)(src + (size_t)i * 8);
    float4 b = *(const float4*)(src + (size_t)i * 8 + 4);
    __half2 h[4];
    h[0] = __floats2half2_rn(a.x, a.y); h[1] = __floats2half2_rn(a.z, a.w);
    h[2] = __floats2half2_rn(b.x, b.y); h[3] = __floats2half2_rn(b.z, b.w);
    *(uint4*)(dst + (size_t)i * 8) = *(uint4*)h;
}

// ---------------------------------------------------------------------------
// fp16 single-pass GEMM-NT + bias:  C[M,N] = A[M,K] @ B[N,K]^T + bias[N]
// 128x128 CTA tile, BK=64, 8 warps (2x4), warp tile 64x32, cp.async 2-stage.
// MODE 0: fp32 out.  MODE 2: fp16 out.
// ---------------------------------------------------------------------------
#define GST    72                    // fp16 row stride (144 B = 9*16 B)
#define GTILE  (128 * GST * 2)       // 18432 B
#define GSTG   (2 * GTILE)           // 36864 B per stage

template<int MODE>
__global__ void __launch_bounds__(256) gemm_f16(
    const __half* __restrict__ A, const __half* __restrict__ B,
    const float* __restrict__ bias, float* __restrict__ Cf,
    __half* __restrict__ Ch, int N, int K)
{
    extern __shared__ char smem[];
    const uint32_t sbase = smem_u32(smem);
    const int tid = threadIdx.x, wid = tid >> 5, lane = tid & 31;
    const int bm = blockIdx.y, bn = blockIdx.x;
    const int wm = wid >> 2, wn = wid & 3;

    float acc[4][4][4];
#pragma unroll
    for (int a = 0; a < 4; a++)
#pragma unroll
        for (int b = 0; b < 4; b++)
#pragma unroll
            for (int c = 0; c < 4; c++) acc[a][b][c] = 0.0f;

    // 2 tensors x 128 rows x 64 cols fp16 = 2048 x 16B transfers, 8/thread.
    auto prefetch = [&](int it) {
        const int k0 = it << 6;
        const int buf = it & 1;
#pragma unroll
        for (int i = 0; i < 8; i++) {
            int g = tid + i * 256;           // 0..2047
            int t = g >> 10;                 // 0=A, 1=B (uniform per i)
            int c = g & 1023;
            int row = c >> 3, ch = c & 7;
            const __half* P = t ? B : A;
            int rb = t ? bn * 128 : bm * 128;
            const void* src = P + (size_t)(rb + row) * K + k0 + ch * 8;
            uint32_t dst = sbase + buf * GSTG + t * GTILE
                         + (row * GST + ch * 8) * 2;
            cpa16(dst, src);
        }
        CP_COMMIT();
    };

    const int niter = K >> 6;
    prefetch(0);
    for (int it = 0; it < niter; it++) {
        CP_WAIT0();
        __syncthreads();
        if (it + 1 < niter) prefetch(it + 1);

        const uint32_t tA = sbase + (it & 1) * GSTG;
        const uint32_t tB = tA + GTILE;

        const int ar = lane & 15, ac = (lane >> 4) * 8;
        const int br = (lane & 7) + ((lane & 16) ? 8 : 0);
        const int bc = (lane & 8) ? 8 : 0;

#pragma unroll
        for (int ks = 0; ks < 4; ks++) {
            const int k0 = ks * 16;
            uint32_t ah[4][4], bh[4][2];
#pragma unroll
            for (int mi = 0; mi < 4; mi++)
                ldsm4(ah[mi], tA + ((wm * 64 + mi * 16 + ar) * GST + k0 + ac) * 2);
#pragma unroll
            for (int p = 0; p < 2; p++) {
                uint32_t r[4];
                ldsm4(r, tB + ((wn * 32 + p * 16 + br) * GST + k0 + bc) * 2);
                bh[2*p][0] = r[0]; bh[2*p][1] = r[1];
                bh[2*p+1][0] = r[2]; bh[2*p+1][1] = r[3];
            }
#pragma unroll
            for (int mi = 0; mi < 4; mi++)
#pragma unroll
                for (int ni = 0; ni < 4; ni++)
                    mma_f16(acc[mi][ni], ah[mi], bh[ni]);
        }
    }

    const int r = lane >> 2, q = lane & 3;
#pragma unroll
    for (int mi = 0; mi < 4; mi++) {
#pragma unroll
        for (int ni = 0; ni < 4; ni++) {
            int row = bm * 128 + wm * 64 + mi * 16 + r;
            int col = bn * 128 + wn * 32 + ni * 8 + 2 * q;
            float b0 = bias[col], b1 = bias[col + 1];
            float v0 = acc[mi][ni][0] + b0, v1 = acc[mi][ni][1] + b1;
            float v2 = acc[mi][ni][2] + b0, v3 = acc[mi][ni][3] + b1;
            if (MODE == 0) {
                *(float2*)(Cf + (size_t)row * N + col)       = make_float2(v0, v1);
                *(float2*)(Cf + (size_t)(row + 8) * N + col) = make_float2(v2, v3);
            } else {
                *(__half2*)(Ch + (size_t)row * N + col)       = __floats2half2_rn(v0, v1);
                *(__half2*)(Ch + (size_t)(row + 8) * N + col) = __floats2half2_rn(v2, v3);
            }
        }
    }
}

// ---------------------------------------------------------------------------
// Flash attention, fp16 HMMA. Block = (q-tile 128, b*H+h), 256 threads/8 warps.
// Output: plain fp16.
// ---------------------------------------------------------------------------
#define AST  72
#define ATBF (64 * AST * 2)     // 9216 B per K/V tile
#define QSTG (128 * AST * 2)    // 18432 B

__global__ void __launch_bounds__(256) attn_f16(
    const __half* __restrict__ qkv, __half* __restrict__ oh)
{
    extern __shared__ char smem[];
    const uint32_t sb  = smem_u32(smem);
    const uint32_t sQ  = sb;
    const uint32_t sKV = sb + QSTG;

    const int tid = threadIdx.x, wid = tid >> 5, lane = tid & 31;
    const int qt = blockIdx.x, bh = blockIdx.y, b = bh >> 4, h = bh & 15;

    auto pf = [&](int st) {
        const int buf = st & 1;
#pragma unroll
        for (int i = 0; i < 4; i++) {
            int c  = tid + i * 256;        // 0..1023
            int kv = c >> 9;               // 0=K, 1=V
            int e  = c & 511;
            int row = e >> 3, ch = e & 7;
            const void* src = qkv + ((size_t)((st * 64 + row) * 2 + b)) * QKV_N
                            + (kv ? 2 * EMBED : EMBED) + h * 64 + ch * 8;
            uint32_t dst = sKV + (buf * 2 + kv) * ATBF + (row * AST + ch * 8) * 2;
            cpa16(dst, src);
        }
        CP_COMMIT();
    };

    pf(0);

    const __half2 s2 = __floats2half2_rn(0.125f, 0.125f);
#pragma unroll
    for (int i = 0; i < 4; i++) {
        int c = tid + i * 256;
        int row = c >> 3, ch = c & 7;
        int t = qt * 128 + row;
        uint4 v = *(const uint4*)(qkv + ((size_t)(t * 2 + b)) * QKV_N + h * 64 + ch * 8);
        __half2* p = (__half2*)&v;
#pragma unroll
        for (int j = 0; j < 4; j++) p[j] = __hmul2(p[j], s2);
        *(uint4*)(smem + (row * AST + ch * 8) * 2) = v;
    }
    __syncthreads();

    uint32_t qf[4][4];
    {
        const int ar = lane & 15, ac = (lane >> 4) * 8;
#pragma unroll
        for (int kt = 0; kt < 4; kt++)
            ldsm4(qf[kt], sQ + ((wid * 16 + ar) * AST + kt * 16 + ac) * 2);
    }

    float O[8][4];
#pragma unroll
    for (int i = 0; i < 8; i++)
#pragma unroll
        for (int j = 0; j < 4; j++) O[i][j] = 0.0f;
    float m0 = -CUDART_INF_F, m1 = -CUDART_INF_F, l0 = 0.0f, l1 = 0.0f;

    const int br = (lane & 7) + ((lane & 16) ? 8 : 0);
    const int bc = (lane & 8) ? 8 : 0;
    const int vr = lane & 15, vc = (lane >> 4) * 8;

    for (int st = 0; st < TLEN / 64; st++) {
        CP_WAIT0();
        __syncthreads();
        if (st + 1 < TLEN / 64) pf(st + 1);

        const uint32_t sK = sKV + ((st & 1) * 2) * ATBF;
        const uint32_t sV = sK + ATBF;

        float s4[8][4];
#pragma unroll
        for (int i = 0; i < 8; i++)
#pragma unroll
            for (int j = 0; j < 4; j++) s4[i][j] = 0.0f;

#pragma unroll
        for (int kt = 0; kt < 4; kt++) {
            uint32_t kh[8][2];
#pragma unroll
            for (int p = 0; p < 4; p++) {
                uint32_t r[4];
                ldsm4(r, sK + ((p * 16 + br) * AST + kt * 16 + bc) * 2);
                kh[2*p][0] = r[0]; kh[2*p][1] = r[1];
                kh[2*p+1][0] = r[2]; kh[2*p+1][1] = r[3];
            }
#pragma unroll
            for (int nt = 0; nt < 8; nt++)
                mma_f16(s4[nt], qf[kt], kh[nt]);
        }

        float mx0 = -CUDART_INF_F, mx1 = -CUDART_INF_F;
#pragma unroll
        for (int nt = 0; nt < 8; nt++) {
            mx0 = fmaxf(mx0, fmaxf(s4[nt][0], s4[nt][1]));
            mx1 = fmaxf(mx1, fmaxf(s4[nt][2], s4[nt][3]));
        }
        mx0 = fmaxf(mx0, __shfl_xor_sync(0xffffffffu, mx0, 1));
        mx0 = fmaxf(mx0, __shfl_xor_sync(0xffffffffu, mx0, 2));
        mx1 = fmaxf(mx1, __shfl_xor_sync(0xffffffffu, mx1, 1));
        mx1 = fmaxf(mx1, __shfl_xor_sync(0xffffffffu, mx1, 2));

        float mn0 = fmaxf(m0, mx0), mn1 = fmaxf(m1, mx1);
        float a0 = __expf(m0 - mn0), a1 = __expf(m1 - mn1);
        m0 = mn0; m1 = mn1;

        uint32_t pa[4][4];
        float sum0 = 0.0f, sum1 = 0.0f;
#pragma unroll
        for (int jj = 0; jj < 4; jj++) {
            float p00 = __expf(s4[2*jj][0]   - mn0), p01 = __expf(s4[2*jj][1]   - mn0);
            float p02 = __expf(s4[2*jj][2]   - mn1), p03 = __expf(s4[2*jj][3]   - mn1);
            float p10 = __expf(s4[2*jj+1][0] - mn0), p11 = __expf(s4[2*jj+1][1] - mn0);
            float p12 = __expf(s4[2*jj+1][2] - mn1), p13 = __expf(s4[2*jj+1][3] - mn1);
            pa[jj][0] = packh(p00, p01);
            pa[jj][1] = packh(p02, p03);
            pa[jj][2] = packh(p10, p11);
            pa[jj][3] = packh(p12, p13);
            float2 f;
            f = __half22float2(*(__half2*)&pa[jj][0]); sum0 += f.x + f.y;
            f = __half22float2(*(__half2*)&pa[jj][2]); sum0 += f.x + f.y;
            f = __half22float2(*(__half2*)&pa[jj][1]); sum1 += f.x + f.y;
            f = __half22float2(*(__half2*)&pa[jj][3]); sum1 += f.x + f.y;
        }
        sum0 += __shfl_xor_sync(0xffffffffu, sum0, 1);
        sum0 += __shfl_xor_sync(0xffffffffu, sum0, 2);
        sum1 += __shfl_xor_sync(0xffffffffu, sum1, 1);
        sum1 += __shfl_xor_sync(0xffffffffu, sum1, 2);
        l0 = l0 * a0 + sum0;
        l1 = l1 * a1 + sum1;
#pragma unroll
        for (int nt = 0; nt < 8; nt++) {
            O[nt][0] *= a0; O[nt][1] *= a0; O[nt][2] *= a1; O[nt][3] *= a1;
        }

#pragma unroll
        for (int kt = 0; kt < 4; kt++) {
#pragma unroll
            for (int p = 0; p < 4; p++) {
                uint32_t r[4];
                ldsm4t(r, sV + ((kt * 16 + vr) * AST + p * 16 + vc) * 2);
                mma_f16(O[2*p],   pa[kt], r);
                mma_f16(O[2*p+1], pa[kt], r + 2);
            }
        }
    }

    const float inv0 = 1.0f / l0, inv1 = 1.0f / l1;
    const int r = lane >> 2, q = lane & 3;
    const int t0 = qt * 128 + wid * 16 + r;
#pragma unroll
    for (int nt = 0; nt < 8; nt++) {
        int d = nt * 8 + 2 * q;
        size_t i0 = ((size_t)(t0 * 2 + b)) * EMBED + h * 64 + d;
        size_t i1 = ((size_t)((t0 + 8) * 2 + b)) * EMBED + h * 64 + d;
        *(__half2*)(oh + i0) = __floats2half2_rn(O[nt][0] * inv0, O[nt][1] * inv0);
        *(__half2*)(oh + i1) = __floats2half2_rn(O[nt][2] * inv1, O[nt][3] * inv1);
    }
}

// ---------------------------------------------------------------------------
extern "C" void kernel_launch(void* const* d_in, const int* in_sizes, int n_in,
                              void* d_out, int out_size)
{
    const float* x     = (const float*)d_in[0];
    const float* w_in  = (const float*)d_in[1];
    const float* b_in  = (const float*)d_in[2];
    const float* w_out = (const float*)d_in[3];
    const float* b_out = (const float*)d_in[4];
    float* out = (float*)d_out;

    void *xh, *winh, *woh, *qkvh, *ah;
    cudaGetSymbolAddress(&xh, g_xh);
    cudaGetSymbolAddress(&winh, g_winh);
    cudaGetSymbolAddress(&woh, g_woh);
    cudaGetSymbolAddress(&qkvh, g_qkvh);
    cudaGetSymbolAddress(&ah, g_ah);

    const int gemm_smem = 2 * GSTG;                   // 73728
    const int attn_smem = QSTG + 4 * ATBF;            // 55296
    cudaFuncSetAttribute(gemm_f16<0>,
        cudaFuncAttributeMaxDynamicSharedMemorySize, gemm_smem);
    cudaFuncSetAttribute(gemm_f16<2>,
        cudaFuncAttributeMaxDynamicSharedMemorySize, gemm_smem);
    cudaFuncSetAttribute(attn_f16,
        cudaFuncAttributeMaxDynamicSharedMemorySize, attn_smem);

    int n8 = MROWS * EMBED / 8;
    conv_f16<<<(n8 + 255) / 256, 256>>>(x, (__half*)xh, n8);
    n8 = QKV_N * EMBED / 8;
    conv_f16<<<(n8 + 255) / 256, 256>>>(w_in, (__half*)winh, n8);
    n8 = EMBED * EMBED / 8;
    conv_f16<<<(n8 + 255) / 256, 256>>>(w_out, (__half*)woh, n8);

    // 1) QKV projection -> fp16 qkv
    gemm_f16<2><<<dim3(QKV_N / 128, MROWS / 128), 256, gemm_smem>>>(
        (const __half*)xh, (const __half*)winh, b_in,
        nullptr, (__half*)qkvh, QKV_N, EMBED);

    // 2) attention -> fp16
    attn_f16<<<dim3(TLEN / 128, BSZ * NHEAD), 256, attn_smem>>>(
        (const __half*)qkvh, (__half*)ah);

    // 3) output projection -> fp32 out
    gemm_f16<0><<<dim3(EMBED / 128, MROWS / 128), 256, gemm_smem>>>(
        (const __half*)ah, (const __half*)woh, b_out,
        out, nullptr, EMBED, EMBED);
}

// round 11
// speedup vs baseline: 1.7850x; 1.0147x over previous
#include <cuda_runtime.h>
#include <cuda_fp16.h>
#include <math_constants.h>
#include <cstdint>

// ---------------------------------------------------------------------------
// MultiheadAttention (T=2048, B=2, E=1024, H=16, D=64) fp32, all-fp16 HMMA:
//   convert x,W to fp16 -> qkv GEMM (1-pass) -> flash attn (fp16, log2-domain
//   softmax via ex2.approx.f16x2) -> out GEMM (1-pass, fp32 epilogue)
// ---------------------------------------------------------------------------

#define EMBED   1024
#define NHEAD   16
#define HDIM    64
#define TLEN    2048
#define BSZ     2
#define MROWS   4096
#define QKV_N   3072

// ------------------------------- scratch -----------------------------------
__device__ __half g_xh  [(size_t)MROWS * EMBED];
__device__ __half g_winh[(size_t)QKV_N * EMBED];
__device__ __half g_woh [(size_t)EMBED * EMBED];
__device__ __half g_qkvh[(size_t)MROWS * QKV_N];
__device__ __half g_ah  [(size_t)MROWS * EMBED];

// --------------------------- asm helpers -----------------------------------
__device__ __forceinline__ uint32_t smem_u32(const void* p) {
    uint32_t a;
    asm("{ .reg .u64 t; cvta.to.shared.u64 t, %1; cvt.u32.u64 %0, t; }"
        : "=r"(a) : "l"(p));
    return a;
}
__device__ __forceinline__ void ldsm4(uint32_t* r, uint32_t a) {
    asm volatile("ldmatrix.sync.aligned.m8n8.x4.shared.b16 {%0,%1,%2,%3}, [%4];"
        : "=r"(r[0]), "=r"(r[1]), "=r"(r[2]), "=r"(r[3]) : "r"(a));
}
__device__ __forceinline__ void ldsm4t(uint32_t* r, uint32_t a) {
    asm volatile("ldmatrix.sync.aligned.m8n8.x4.trans.shared.b16 {%0,%1,%2,%3}, [%4];"
        : "=r"(r[0]), "=r"(r[1]), "=r"(r[2]), "=r"(r[3]) : "r"(a));
}
__device__ __forceinline__ void mma_f16(float* c, const uint32_t* a, const uint32_t* b) {
    asm volatile(
        "mma.sync.aligned.m16n8k16.row.col.f32.f16.f16.f32 "
        "{%0,%1,%2,%3}, {%4,%5,%6,%7}, {%8,%9}, {%0,%1,%2,%3};"
        : "+f"(c[0]), "+f"(c[1]), "+f"(c[2]), "+f"(c[3])
        : "r"(a[0]), "r"(a[1]), "r"(a[2]), "r"(a[3]), "r"(b[0]), "r"(b[1]));
}
__device__ __forceinline__ void cpa16(uint32_t dst, const void* src) {
    asm volatile("cp.async.cg.shared.global [%0], [%1], 16;" :: "r"(dst), "l"(src));
}
#define CP_COMMIT() asm volatile("cp.async.commit_group;")
#define CP_WAIT0()  asm volatile("cp.async.wait_group 0;")

__device__ __forceinline__ uint32_t packh(float x, float y) {
    __half2 t = __floats2half2_rn(x, y);
    return *(uint32_t*)&t;
}
// two fp16 exponentials (base-2) in one MUFU op
__device__ __forceinline__ uint32_t h2ex2(uint32_t x) {
    uint32_t y;
    asm("ex2.approx.f16x2 %0, %1;" : "=r"(y) : "r"(x));
    return y;
}

// ---------------------------------------------------------------------------
__global__ void __launch_bounds__(256) conv_f16(
    const float* __restrict__ src, __half* __restrict__ dst, int n8)
{
    int i = blockIdx.x * 256 + threadIdx.x;
    if (i >= n8) return;
    float4 a = *(const float4*)(src + (size_t)i * 8);
    float4 b = *(const float4*)(src + (size_t)i * 8 + 4);
    __half2 h[4];
    h[0] = __floats2half2_rn(a.x, a.y); h[1] = __floats2half2_rn(a.z, a.w);
    h[2] = __floats2half2_rn(b.x, b.y); h[3] = __floats2half2_rn(b.z, b.w);
    *(uint4*)(dst + (size_t)i * 8) = *(uint4*)h;
}

// ---------------------------------------------------------------------------
// fp16 single-pass GEMM-NT + bias:  C[M,N] = A[M,K] @ B[N,K]^T + bias[N]
// 128x128 CTA tile, BK=64, 8 warps (2x4), warp tile 64x32, cp.async 2-stage.
// MODE 0: fp32 out.  MODE 2: fp16 out.
// ---------------------------------------------------------------------------
#define GST    72                    // fp16 row stride (144 B = 9*16 B)
#define GTILE  (128 * GST * 2)       // 18432 B
#define GSTG   (2 * GTILE)           // 36864 B per stage

template<int MODE>
__global__ void __launch_bounds__(256) gemm_f16(
    const __half* __restrict__ A, const __half* __restrict__ B,
    const float* __restrict__ bias, float* __restrict__ Cf,
    __half* __restrict__ Ch, int N, int K)
{
    extern __shared__ char smem[];
    const uint32_t sbase = smem_u32(smem);
    const int tid = threadIdx.x, wid = tid >> 5, lane = tid & 31;
    const int bm = blockIdx.y, bn = blockIdx.x;
    const int wm = wid >> 2, wn = wid & 3;

    float acc[4][4][4];
#pragma unroll
    for (int a = 0; a < 4; a++)
#pragma unroll
        for (int b = 0; b < 4; b++)
#pragma unroll
            for (int c = 0; c < 4; c++) acc[a][b][c] = 0.0f;

    auto prefetch = [&](int it) {
        const int k0 = it << 6;
        const int buf = it & 1;
#pragma unroll
        for (int i = 0; i < 8; i++) {
            int g = tid + i * 256;           // 0..2047
            int t = g >> 10;                 // 0=A, 1=B (uniform per i)
            int c = g & 1023;
            int row = c >> 3, ch = c & 7;
            const __half* P = t ? B : A;
            int rb = t ? bn * 128 : bm * 128;
            const void* src = P + (size_t)(rb + row) * K + k0 + ch * 8;
            uint32_t dst = sbase + buf * GSTG + t * GTILE
                         + (row * GST + ch * 8) * 2;
            cpa16(dst, src);
        }
        CP_COMMIT();
    };

    const int niter = K >> 6;
    prefetch(0);
    for (int it = 0; it < niter; it++) {
        CP_WAIT0();
        __syncthreads();
        if (it + 1 < niter) prefetch(it + 1);

        const uint32_t tA = sbase + (it & 1) * GSTG;
        const uint32_t tB = tA + GTILE;

        const int ar = lane & 15, ac = (lane >> 4) * 8;
        const int br = (lane & 7) + ((lane & 16) ? 8 : 0);
        const int bc = (lane & 8) ? 8 : 0;

#pragma unroll
        for (int ks = 0; ks < 4; ks++) {
            const int k0 = ks * 16;
            uint32_t ah[4][4], bh[4][2];
#pragma unroll
            for (int mi = 0; mi < 4; mi++)
                ldsm4(ah[mi], tA + ((wm * 64 + mi * 16 + ar) * GST + k0 + ac) * 2);
#pragma unroll
            for (int p = 0; p < 2; p++) {
                uint32_t r[4];
                ldsm4(r, tB + ((wn * 32 + p * 16 + br) * GST + k0 + bc) * 2);
                bh[2*p][0] = r[0]; bh[2*p][1] = r[1];
                bh[2*p+1][0] = r[2]; bh[2*p+1][1] = r[3];
            }
#pragma unroll
            for (int mi = 0; mi < 4; mi++)
#pragma unroll
                for (int ni = 0; ni < 4; ni++)
                    mma_f16(acc[mi][ni], ah[mi], bh[ni]);
        }
    }

    const int r = lane >> 2, q = lane & 3;
#pragma unroll
    for (int mi = 0; mi < 4; mi++) {
#pragma unroll
        for (int ni = 0; ni < 4; ni++) {
            int row = bm * 128 + wm * 64 + mi * 16 + r;
            int col = bn * 128 + wn * 32 + ni * 8 + 2 * q;
            float b0 = bias[col], b1 = bias[col + 1];
            float v0 = acc[mi][ni][0] + b0, v1 = acc[mi][ni][1] + b1;
            float v2 = acc[mi][ni][2] + b0, v3 = acc[mi][ni][3] + b1;
            if (MODE == 0) {
                *(float2*)(Cf + (size_t)row * N + col)       = make_float2(v0, v1);
                *(float2*)(Cf + (size_t)(row + 8) * N + col) = make_float2(v2, v3);
            } else {
                *(__half2*)(Ch + (size_t)row * N + col)       = __floats2half2_rn(v0, v1);
                *(__half2*)(Ch + (size_t)(row + 8) * N + col) = __floats2half2_rn(v2, v3);
            }
        }
    }
}

// ---------------------------------------------------------------------------
// Flash attention, fp16 HMMA, log2-domain softmax (ex2.approx.f16x2).
// Block = (q-tile 128, b*H+h), 256 threads/8 warps.  Output: plain fp16.
// ---------------------------------------------------------------------------
#define AST  72
#define ATBF (64 * AST * 2)     // 9216 B per K/V tile
#define QSTG (128 * AST * 2)    // 18432 B

__global__ void __launch_bounds__(256) attn_f16(
    const __half* __restrict__ qkv, __half* __restrict__ oh)
{
    extern __shared__ char smem[];
    const uint32_t sb  = smem_u32(smem);
    const uint32_t sQ  = sb;
    const uint32_t sKV = sb + QSTG;

    const int tid = threadIdx.x, wid = tid >> 5, lane = tid & 31;
    const int qt = blockIdx.x, bh = blockIdx.y, b = bh >> 4, h = bh & 15;

    auto pf = [&](int st) {
        const int buf = st & 1;
#pragma unroll
        for (int i = 0; i < 4; i++) {
            int c  = tid + i * 256;        // 0..1023
            int kv = c >> 9;               // 0=K, 1=V
            int e  = c & 511;
            int row = e >> 3, ch = e & 7;
            const void* src = qkv + ((size_t)((st * 64 + row) * 2 + b)) * QKV_N
                            + (kv ? 2 * EMBED : EMBED) + h * 64 + ch * 8;
            uint32_t dst = sKV + (buf * 2 + kv) * ATBF + (row * AST + ch * 8) * 2;
            cpa16(dst, src);
        }
        CP_COMMIT();
    };

    pf(0);

    // Q scaled by 0.125 * log2(e): scores leave QK^T already in log2 domain.
    const __half2 s2 = __floats2half2_rn(0.1803368801f, 0.1803368801f);
#pragma unroll
    for (int i = 0; i < 4; i++) {
        int c = tid + i * 256;
        int row = c >> 3, ch = c & 7;
        int t = qt * 128 + row;
        uint4 v = *(const uint4*)(qkv + ((size_t)(t * 2 + b)) * QKV_N + h * 64 + ch * 8);
        __half2* p = (__half2*)&v;
#pragma unroll
        for (int j = 0; j < 4; j++) p[j] = __hmul2(p[j], s2);
        *(uint4*)(smem + (row * AST + ch * 8) * 2) = v;
    }
    __syncthreads();

    uint32_t qf[4][4];
    {
        const int ar = lane & 15, ac = (lane >> 4) * 8;
#pragma unroll
        for (int kt = 0; kt < 4; kt++)
            ldsm4(qf[kt], sQ + ((wid * 16 + ar) * AST + kt * 16 + ac) * 2);
    }

    float O[8][4];
#pragma unroll
    for (int i = 0; i < 8; i++)
#pragma unroll
        for (int j = 0; j < 4; j++) O[i][j] = 0.0f;
    float m0 = -CUDART_INF_F, m1 = -CUDART_INF_F, l0 = 0.0f, l1 = 0.0f;

    const int br = (lane & 7) + ((lane & 16) ? 8 : 0);
    const int bc = (lane & 8) ? 8 : 0;
    const int vr = lane & 15, vc = (lane >> 4) * 8;

    for (int st = 0; st < TLEN / 64; st++) {
        CP_WAIT0();
        __syncthreads();
        if (st + 1 < TLEN / 64) pf(st + 1);

        const uint32_t sK = sKV + ((st & 1) * 2) * ATBF;
        const uint32_t sV = sK + ATBF;

        float s4[8][4];
#pragma unroll
        for (int i = 0; i < 8; i++)
#pragma unroll
            for (int j = 0; j < 4; j++) s4[i][j] = 0.0f;

#pragma unroll
        for (int kt = 0; kt < 4; kt++) {
            uint32_t kh[8][2];
#pragma unroll
            for (int p = 0; p < 4; p++) {
                uint32_t r[4];
                ldsm4(r, sK + ((p * 16 + br) * AST + kt * 16 + bc) * 2);
                kh[2*p][0] = r[0]; kh[2*p][1] = r[1];
                kh[2*p+1][0] = r[2]; kh[2*p+1][1] = r[3];
            }
#pragma unroll
            for (int nt = 0; nt < 8; nt++)
                mma_f16(s4[nt], qf[kt], kh[nt]);
        }

        float mx0 = -CUDART_INF_F, mx1 = -CUDART_INF_F;
#pragma unroll
        for (int nt = 0; nt < 8; nt++) {
            mx0 = fmaxf(mx0, fmaxf(s4[nt][0], s4[nt][1]));
            mx1 = fmaxf(mx1, fmaxf(s4[nt][2], s4[nt][3]));
        }
        mx0 = fmaxf(mx0, __shfl_xor_sync(0xffffffffu, mx0, 1));
        mx0 = fmaxf(mx0, __shfl_xor_sync(0xffffffffu, mx0, 2));
        mx1 = fmaxf(mx1, __shfl_xor_sync(0xffffffffu, mx1, 1));
        mx1 = fmaxf(mx1, __shfl_xor_sync(0xffffffffu, mx1, 2));

        float mn0 = fmaxf(m0, mx0), mn1 = fmaxf(m1, mx1);
        float a0 = exp2f(m0 - mn0), a1 = exp2f(m1 - mn1);
        m0 = mn0; m1 = mn1;

        // p = 2^(s - m), two at a time on the SFU (fp16x2)
        uint32_t pa[4][4];
        float sum0 = 0.0f, sum1 = 0.0f;
#pragma unroll
        for (int jj = 0; jj < 4; jj++) {
            pa[jj][0] = h2ex2(packh(s4[2*jj][0]   - mn0, s4[2*jj][1]   - mn0));
            pa[jj][1] = h2ex2(packh(s4[2*jj][2]   - mn1, s4[2*jj][3]   - mn1));
            pa[jj][2] = h2ex2(packh(s4[2*jj+1][0] - mn0, s4[2*jj+1][1] - mn0));
            pa[jj][3] = h2ex2(packh(s4[2*jj+1][2] - mn1, s4[2*jj+1][3] - mn1));
            // accumulate l from the SAME fp16 p values fed to PV
            float2 f;
            f = __half22float2(*(__half2*)&pa[jj][0]); sum0 += f.x + f.y;
            f = __half22float2(*(__half2*)&pa[jj][2]); sum0 += f.x + f.y;
            f = __half22float2(*(__half2*)&pa[jj][1]); sum1 += f.x + f.y;
            f = __half22float2(*(__half2*)&pa[jj][3]); sum1 += f.x + f.y;
        }
        sum0 += __shfl_xor_sync(0xffffffffu, sum0, 1);
        sum0 += __shfl_xor_sync(0xffffffffu, sum0, 2);
        sum1 += __shfl_xor_sync(0xffffffffu, sum1, 1);
        sum1 += __shfl_xor_sync(0xffffffffu, sum1, 2);
        l0 = l0 * a0 + sum0;
        l1 = l1 * a1 + sum1;
#pragma unroll
        for (int nt = 0; nt < 8; nt++) {
            O[nt][0] *= a0; O[nt][1] *= a0; O[nt][2] *= a1; O[nt][3] *= a1;
        }

#pragma unroll
        for (int kt = 0; kt < 4; kt++) {
#pragma unroll
            for (int p = 0; p < 4; p++) {
                uint32_t r[4];
                ldsm4t(r, sV + ((kt * 16 + vr) * AST + p * 16 + vc) * 2);
                mma_f16(O[2*p],   pa[kt], r);
                mma_f16(O[2*p+1], pa[kt], r + 2);
            }
        }
    }

    const float inv0 = 1.0f / l0, inv1 = 1.0f / l1;
    const int r = lane >> 2, q = lane & 3;
    const int t0 = qt * 128 + wid * 16 + r;
#pragma unroll
    for (int nt = 0; nt < 8; nt++) {
        int d = nt * 8 + 2 * q;
        size_t i0 = ((size_t)(t0 * 2 + b)) * EMBED + h * 64 + d;
        size_t i1 = ((size_t)((t0 + 8) * 2 + b)) * EMBED + h * 64 + d;
        *(__half2*)(oh + i0) = __floats2half2_rn(O[nt][0] * inv0, O[nt][1] * inv0);
        *(__half2*)(oh + i1) = __floats2half2_rn(O[nt][2] * inv1, O[nt][3] * inv1);
    }
}

// ---------------------------------------------------------------------------
extern "C" void kernel_launch(void* const* d_in, const int* in_sizes, int n_in,
                              void* d_out, int out_size)
{
    const float* x     = (const float*)d_in[0];
    const float* w_in  = (const float*)d_in[1];
    const float* b_in  = (const float*)d_in[2];
    const float* w_out = (const float*)d_in[3];
    const float* b_out = (const float*)d_in[4];
    float* out = (float*)d_out;

    void *xh, *winh, *woh, *qkvh, *ah;
    cudaGetSymbolAddress(&xh, g_xh);
    cudaGetSymbolAddress(&winh, g_winh);
    cudaGetSymbolAddress(&woh, g_woh);
    cudaGetSymbolAddress(&qkvh, g_qkvh);
    cudaGetSymbolAddress(&ah, g_ah);

    const int gemm_smem = 2 * GSTG;                   // 73728
    const int attn_smem = QSTG + 4 * ATBF;            // 55296
    cudaFuncSetAttribute(gemm_f16<0>,
        cudaFuncAttributeMaxDynamicSharedMemorySize, gemm_smem);
    cudaFuncSetAttribute(gemm_f16<2>,
        cudaFuncAttributeMaxDynamicSharedMemorySize, gemm_smem);
    cudaFuncSetAttribute(attn_f16,
        cudaFuncAttributeMaxDynamicSharedMemorySize, attn_smem);

    int n8 = MROWS * EMBED / 8;
    conv_f16<<<(n8 + 255) / 256, 256>>>(x, (__half*)xh, n8);
    n8 = QKV_N * EMBED / 8;
    conv_f16<<<(n8 + 255) / 256, 256>>>(w_in, (__half*)winh, n8);
    n8 = EMBED * EMBED / 8;
    conv_f16<<<(n8 + 255) / 256, 256>>>(w_out, (__half*)woh, n8);

    // 1) QKV projection -> fp16 qkv
    gemm_f16<2><<<dim3(QKV_N / 128, MROWS / 128), 256, gemm_smem>>>(
        (const __half*)xh, (const __half*)winh, b_in,
        nullptr, (__half*)qkvh, QKV_N, EMBED);

    // 2) attention -> fp16
    attn_f16<<<dim3(TLEN / 128, BSZ * NHEAD), 256, attn_smem>>>(
        (const __half*)qkvh, (__half*)ah);

    // 3) output projection -> fp32 out
    gemm_f16<0><<<dim3(EMBED / 128, MROWS / 128), 256, gemm_smem>>>(
        (const __half*)ah, (const __half*)woh, b_out,
        out, nullptr, EMBED, EMBED);
}

// round 12
// speedup vs baseline: 1.7852x; 1.0001x over previous
#include <cuda_runtime.h>
#include <cuda_fp16.h>
#include <math_constants.h>
#include <cstdint>

// ---------------------------------------------------------------------------
// MultiheadAttention (T=2048, B=2, E=1024, H=16, D=64) fp32, all-fp16 HMMA.
// R12: smem-traffic reduction — 64x64 GEMM warp tiles (32 FLOP/B), attention
// warps own 32 q-rows each (K/V tiles read 4x not 8x per stage).
// ---------------------------------------------------------------------------

#define EMBED   1024
#define NHEAD   16
#define HDIM    64
#define TLEN    2048
#define BSZ     2
#define MROWS   4096
#define QKV_N   3072

// ------------------------------- scratch -----------------------------------
__device__ __half g_xh  [(size_t)MROWS * EMBED];
__device__ __half g_winh[(size_t)QKV_N * EMBED];
__device__ __half g_woh [(size_t)EMBED * EMBED];
__device__ __half g_qkvh[(size_t)MROWS * QKV_N];
__device__ __half g_ah  [(size_t)MROWS * EMBED];

// --------------------------- asm helpers -----------------------------------
__device__ __forceinline__ uint32_t smem_u32(const void* p) {
    uint32_t a;
    asm("{ .reg .u64 t; cvta.to.shared.u64 t, %1; cvt.u32.u64 %0, t; }"
        : "=r"(a) : "l"(p));
    return a;
}
__device__ __forceinline__ void ldsm4(uint32_t* r, uint32_t a) {
    asm volatile("ldmatrix.sync.aligned.m8n8.x4.shared.b16 {%0,%1,%2,%3}, [%4];"
        : "=r"(r[0]), "=r"(r[1]), "=r"(r[2]), "=r"(r[3]) : "r"(a));
}
__device__ __forceinline__ void ldsm4t(uint32_t* r, uint32_t a) {
    asm volatile("ldmatrix.sync.aligned.m8n8.x4.trans.shared.b16 {%0,%1,%2,%3}, [%4];"
        : "=r"(r[0]), "=r"(r[1]), "=r"(r[2]), "=r"(r[3]) : "r"(a));
}
__device__ __forceinline__ void mma_f16(float* c, const uint32_t* a, const uint32_t* b) {
    asm volatile(
        "mma.sync.aligned.m16n8k16.row.col.f32.f16.f16.f32 "
        "{%0,%1,%2,%3}, {%4,%5,%6,%7}, {%8,%9}, {%0,%1,%2,%3};"
        : "+f"(c[0]), "+f"(c[1]), "+f"(c[2]), "+f"(c[3])
        : "r"(a[0]), "r"(a[1]), "r"(a[2]), "r"(a[3]), "r"(b[0]), "r"(b[1]));
}
__device__ __forceinline__ void cpa16(uint32_t dst, const void* src) {
    asm volatile("cp.async.cg.shared.global [%0], [%1], 16;" :: "r"(dst), "l"(src));
}
#define CP_COMMIT() asm volatile("cp.async.commit_group;")
#define CP_WAIT0()  asm volatile("cp.async.wait_group 0;")

__device__ __forceinline__ uint32_t packh(float x, float y) {
    __half2 t = __floats2half2_rn(x, y);
    return *(uint32_t*)&t;
}
__device__ __forceinline__ uint32_t h2ex2(uint32_t x) {
    uint32_t y;
    asm("ex2.approx.f16x2 %0, %1;" : "=r"(y) : "r"(x));
    return y;
}

// ---------------------------------------------------------------------------
__global__ void __launch_bounds__(256) conv_f16(
    const float* __restrict__ src, __half* __restrict__ dst, int n8)
{
    int i = blockIdx.x * 256 + threadIdx.x;
    if (i >= n8) return;
    float4 a = *(const float4*)(src + (size_t)i * 8);
    float4 b = *(const float4*)(src + (size_t)i * 8 + 4);
    __half2 h[4];
    h[0] = __floats2half2_rn(a.x, a.y); h[1] = __floats2half2_rn(a.z, a.w);
    h[2] = __floats2half2_rn(b.x, b.y); h[3] = __floats2half2_rn(b.z, b.w);
    *(uint4*)(dst + (size_t)i * 8) = *(uint4*)h;
}

// ---------------------------------------------------------------------------
// fp16 GEMM-NT + bias: 128x128 CTA tile, BK=64, 4 warps (2x2), 64x64 warp
// tile, cp.async 2-stage. MODE 0: fp32 out.  MODE 2: fp16 out.
// ---------------------------------------------------------------------------
#define GST    72
#define GTILE  (128 * GST * 2)       // 18432 B
#define GSTG   (2 * GTILE)           // 36864 B per stage

template<int MODE>
__global__ void __launch_bounds__(128, 2) gemm_f16(
    const __half* __restrict__ A, const __half* __restrict__ B,
    const float* __restrict__ bias, float* __restrict__ Cf,
    __half* __restrict__ Ch, int N, int K)
{
    extern __shared__ char smem[];
    const uint32_t sbase = smem_u32(smem);
    const int tid = threadIdx.x, wid = tid >> 5, lane = tid & 31;
    const int bm = blockIdx.y, bn = blockIdx.x;
    const int wm = wid >> 1, wn = wid & 1;

    float acc[4][8][4];
#pragma unroll
    for (int a = 0; a < 4; a++)
#pragma unroll
        for (int b = 0; b < 8; b++)
#pragma unroll
            for (int c = 0; c < 4; c++) acc[a][b][c] = 0.0f;

    // 2 tensors x 128 rows x 64 cols fp16 = 2048 x 16B transfers, 16/thread.
    auto prefetch = [&](int it) {
        const int k0 = it << 6;
        const int buf = it & 1;
#pragma unroll
        for (int i = 0; i < 16; i++) {
            int g = tid + i * 128;           // 0..2047
            int t = g >> 10;                 // 0=A, 1=B (uniform per i)
            int c = g & 1023;
            int row = c >> 3, ch = c & 7;
            const __half* P = t ? B : A;
            int rb = t ? bn * 128 : bm * 128;
            const void* src = P + (size_t)(rb + row) * K + k0 + ch * 8;
            uint32_t dst = sbase + buf * GSTG + t * GTILE
                         + (row * GST + ch * 8) * 2;
            cpa16(dst, src);
        }
        CP_COMMIT();
    };

    const int niter = K >> 6;
    prefetch(0);
    for (int it = 0; it < niter; it++) {
        CP_WAIT0();
        __syncthreads();
        if (it + 1 < niter) prefetch(it + 1);

        const uint32_t tA = sbase + (it & 1) * GSTG;
        const uint32_t tB = tA + GTILE;

        const int ar = lane & 15, ac = (lane >> 4) * 8;
        const int br = (lane & 7) + ((lane & 16) ? 8 : 0);
        const int bc = (lane & 8) ? 8 : 0;

#pragma unroll
        for (int ks = 0; ks < 4; ks++) {
            const int k0 = ks * 16;
            uint32_t ah[4][4], bh[8][2];
#pragma unroll
            for (int mi = 0; mi < 4; mi++)
                ldsm4(ah[mi], tA + ((wm * 64 + mi * 16 + ar) * GST + k0 + ac) * 2);
#pragma unroll
            for (int p = 0; p < 4; p++) {
                uint32_t r[4];
                ldsm4(r, tB + ((wn * 64 + p * 16 + br) * GST + k0 + bc) * 2);
                bh[2*p][0] = r[0]; bh[2*p][1] = r[1];
                bh[2*p+1][0] = r[2]; bh[2*p+1][1] = r[3];
            }
#pragma unroll
            for (int mi = 0; mi < 4; mi++)
#pragma unroll
                for (int ni = 0; ni < 8; ni++)
                    mma_f16(acc[mi][ni], ah[mi], bh[ni]);
        }
    }

    const int r = lane >> 2, q = lane & 3;
#pragma unroll
    for (int mi = 0; mi < 4; mi++) {
#pragma unroll
        for (int ni = 0; ni < 8; ni++) {
            int row = bm * 128 + wm * 64 + mi * 16 + r;
            int col = bn * 128 + wn * 64 + ni * 8 + 2 * q;
            float b0 = bias[col], b1 = bias[col + 1];
            float v0 = acc[mi][ni][0] + b0, v1 = acc[mi][ni][1] + b1;
            float v2 = acc[mi][ni][2] + b0, v3 = acc[mi][ni][3] + b1;
            if (MODE == 0) {
                *(float2*)(Cf + (size_t)row * N + col)       = make_float2(v0, v1);
                *(float2*)(Cf + (size_t)(row + 8) * N + col) = make_float2(v2, v3);
            } else {
                *(__half2*)(Ch + (size_t)row * N + col)       = __floats2half2_rn(v0, v1);
                *(__half2*)(Ch + (size_t)(row + 8) * N + col) = __floats2half2_rn(v2, v3);
            }
        }
    }
}

// ---------------------------------------------------------------------------
// Flash attention, fp16 HMMA, log2-domain softmax. Block = (q-tile 128,
// b*H+h), 128 threads / 4 warps; warp w owns q rows 32w..32w+31 (K/V tiles
// read by 4 warps instead of 8).
// ---------------------------------------------------------------------------
#define AST  72
#define ATBF (64 * AST * 2)     // 9216 B per K/V tile
#define QSTG (128 * AST * 2)    // 18432 B

__global__ void __launch_bounds__(128) attn_f16(
    const __half* __restrict__ qkv, __half* __restrict__ oh)
{
    extern __shared__ char smem[];
    const uint32_t sb  = smem_u32(smem);
    const uint32_t sQ  = sb;
    const uint32_t sKV = sb + QSTG;

    const int tid = threadIdx.x, wid = tid >> 5, lane = tid & 31;
    const int qt = blockIdx.x, bh = blockIdx.y, b = bh >> 4, h = bh & 15;

    // K tile + V tile per stage = 1024 x 16B transfers, 8/thread.
    auto pf = [&](int st) {
        const int buf = st & 1;
#pragma unroll
        for (int i = 0; i < 8; i++) {
            int c  = tid + i * 128;        // 0..1023
            int kv = c >> 9;               // 0=K, 1=V
            int e  = c & 511;
            int row = e >> 3, ch = e & 7;
            const void* src = qkv + ((size_t)((st * 64 + row) * 2 + b)) * QKV_N
                            + (kv ? 2 * EMBED : EMBED) + h * 64 + ch * 8;
            uint32_t dst = sKV + (buf * 2 + kv) * ATBF + (row * AST + ch * 8) * 2;
            cpa16(dst, src);
        }
        CP_COMMIT();
    };

    pf(0);

    // Q scaled by 0.125 * log2(e): scores leave QK^T in log2 domain.
    const __half2 s2 = __floats2half2_rn(0.1803368801f, 0.1803368801f);
#pragma unroll
    for (int i = 0; i < 8; i++) {
        int c = tid + i * 128;             // 0..1023
        int row = c >> 3, ch = c & 7;
        int t = qt * 128 + row;
        uint4 v = *(const uint4*)(qkv + ((size_t)(t * 2 + b)) * QKV_N + h * 64 + ch * 8);
        __half2* p = (__half2*)&v;
#pragma unroll
        for (int j = 0; j < 4; j++) p[j] = __hmul2(p[j], s2);
        *(uint4*)(smem + (row * AST + ch * 8) * 2) = v;
    }
    __syncthreads();

    // preload Q fragments: 2 m16-frags (rows 32w..32w+15, 32w+16..32w+31)
    uint32_t qf[4][2][4];
    {
        const int ar = lane & 15, ac = (lane >> 4) * 8;
#pragma unroll
        for (int kt = 0; kt < 4; kt++)
#pragma unroll
            for (int mi = 0; mi < 2; mi++)
                ldsm4(qf[kt][mi],
                      sQ + ((wid * 32 + mi * 16 + ar) * AST + kt * 16 + ac) * 2);
    }

    float O[2][8][4];
#pragma unroll
    for (int mi = 0; mi < 2; mi++)
#pragma unroll
        for (int i = 0; i < 8; i++)
#pragma unroll
            for (int j = 0; j < 4; j++) O[mi][i][j] = 0.0f;
    // m/l per thread row-slot: [mi*2 + half]
    float m[4], l[4];
#pragma unroll
    for (int i = 0; i < 4; i++) { m[i] = -CUDART_INF_F; l[i] = 0.0f; }

    const int br = (lane & 7) + ((lane & 16) ? 8 : 0);
    const int bc = (lane & 8) ? 8 : 0;
    const int vr = lane & 15, vc = (lane >> 4) * 8;

    for (int st = 0; st < TLEN / 64; st++) {
        CP_WAIT0();
        __syncthreads();
        if (st + 1 < TLEN / 64) pf(st + 1);

        const uint32_t sK = sKV + ((st & 1) * 2) * ATBF;
        const uint32_t sV = sK + ATBF;

        // ---- S = Q K^T ----
        float s4[2][8][4];
#pragma unroll
        for (int mi = 0; mi < 2; mi++)
#pragma unroll
            for (int i = 0; i < 8; i++)
#pragma unroll
                for (int j = 0; j < 4; j++) s4[mi][i][j] = 0.0f;

#pragma unroll
        for (int kt = 0; kt < 4; kt++) {
            uint32_t kh[8][2];
#pragma unroll
            for (int p = 0; p < 4; p++) {
                uint32_t r[4];
                ldsm4(r, sK + ((p * 16 + br) * AST + kt * 16 + bc) * 2);
                kh[2*p][0] = r[0]; kh[2*p][1] = r[1];
                kh[2*p+1][0] = r[2]; kh[2*p+1][1] = r[3];
            }
#pragma unroll
            for (int mi = 0; mi < 2; mi++)
#pragma unroll
                for (int nt = 0; nt < 8; nt++)
                    mma_f16(s4[mi][nt], qf[kt][mi], kh[nt]);
        }

        // ---- online softmax (per mi: halves 0/1 = rows r, r+8) ----
        uint32_t pa[2][4][4];
#pragma unroll
        for (int mi = 0; mi < 2; mi++) {
            float mx0 = -CUDART_INF_F, mx1 = -CUDART_INF_F;
#pragma unroll
            for (int nt = 0; nt < 8; nt++) {
                mx0 = fmaxf(mx0, fmaxf(s4[mi][nt][0], s4[mi][nt][1]));
                mx1 = fmaxf(mx1, fmaxf(s4[mi][nt][2], s4[mi][nt][3]));
            }
            mx0 = fmaxf(mx0, __shfl_xor_sync(0xffffffffu, mx0, 1));
            mx0 = fmaxf(mx0, __shfl_xor_sync(0xffffffffu, mx0, 2));
            mx1 = fmaxf(mx1, __shfl_xor_sync(0xffffffffu, mx1, 1));
            mx1 = fmaxf(mx1, __shfl_xor_sync(0xffffffffu, mx1, 2));

            float mn0 = fmaxf(m[mi*2],   mx0);
            float mn1 = fmaxf(m[mi*2+1], mx1);
            float a0 = exp2f(m[mi*2]   - mn0);
            float a1 = exp2f(m[mi*2+1] - mn1);
            m[mi*2] = mn0; m[mi*2+1] = mn1;

            float sum0 = 0.0f, sum1 = 0.0f;
#pragma unroll
            for (int jj = 0; jj < 4; jj++) {
                pa[mi][jj][0] = h2ex2(packh(s4[mi][2*jj][0]   - mn0, s4[mi][2*jj][1]   - mn0));
                pa[mi][jj][1] = h2ex2(packh(s4[mi][2*jj][2]   - mn1, s4[mi][2*jj][3]   - mn1));
                pa[mi][jj][2] = h2ex2(packh(s4[mi][2*jj+1][0] - mn0, s4[mi][2*jj+1][1] - mn0));
                pa[mi][jj][3] = h2ex2(packh(s4[mi][2*jj+1][2] - mn1, s4[mi][2*jj+1][3] - mn1));
                float2 f;
                f = __half22float2(*(__half2*)&pa[mi][jj][0]); sum0 += f.x + f.y;
                f = __half22float2(*(__half2*)&pa[mi][jj][2]); sum0 += f.x + f.y;
                f = __half22float2(*(__half2*)&pa[mi][jj][1]); sum1 += f.x + f.y;
                f = __half22float2(*(__half2*)&pa[mi][jj][3]); sum1 += f.x + f.y;
            }
            sum0 += __shfl_xor_sync(0xffffffffu, sum0, 1);
            sum0 += __shfl_xor_sync(0xffffffffu, sum0, 2);
            sum1 += __shfl_xor_sync(0xffffffffu, sum1, 1);
            sum1 += __shfl_xor_sync(0xffffffffu, sum1, 2);
            l[mi*2]   = l[mi*2]   * a0 + sum0;
            l[mi*2+1] = l[mi*2+1] * a1 + sum1;
#pragma unroll
            for (int nt = 0; nt < 8; nt++) {
                O[mi][nt][0] *= a0; O[mi][nt][1] *= a0;
                O[mi][nt][2] *= a1; O[mi][nt][3] *= a1;
            }
        }

        // ---- O += P V ----
#pragma unroll
        for (int kt = 0; kt < 4; kt++) {
#pragma unroll
            for (int p = 0; p < 4; p++) {
                uint32_t r[4];
                ldsm4t(r, sV + ((kt * 16 + vr) * AST + p * 16 + vc) * 2);
#pragma unroll
                for (int mi = 0; mi < 2; mi++) {
                    mma_f16(O[mi][2*p],   pa[mi][kt], r);
                    mma_f16(O[mi][2*p+1], pa[mi][kt], r + 2);
                }
            }
        }
    }

    // ---- epilogue ----
    const int r = lane >> 2, q = lane & 3;
#pragma unroll
    for (int mi = 0; mi < 2; mi++) {
        float inv0 = 1.0f / l[mi*2], inv1 = 1.0f / l[mi*2+1];
        int t0 = qt * 128 + wid * 32 + mi * 16 + r;
#pragma unroll
        for (int nt = 0; nt < 8; nt++) {
            int d = nt * 8 + 2 * q;
            size_t i0 = ((size_t)(t0 * 2 + b)) * EMBED + h * 64 + d;
            size_t i1 = ((size_t)((t0 + 8) * 2 + b)) * EMBED + h * 64 + d;
            *(__half2*)(oh + i0) = __floats2half2_rn(O[mi][nt][0] * inv0,
                                                     O[mi][nt][1] * inv0);
            *(__half2*)(oh + i1) = __floats2half2_rn(O[mi][nt][2] * inv1,
                                                     O[mi][nt][3] * inv1);
        }
    }
}

// ---------------------------------------------------------------------------
extern "C" void kernel_launch(void* const* d_in, const int* in_sizes, int n_in,
                              void* d_out, int out_size)
{
    const float* x     = (const float*)d_in[0];
    const float* w_in  = (const float*)d_in[1];
    const float* b_in  = (const float*)d_in[2];
    const float* w_out = (const float*)d_in[3];
    const float* b_out = (const float*)d_in[4];
    float* out = (float*)d_out;

    void *xh, *winh, *woh, *qkvh, *ah;
    cudaGetSymbolAddress(&xh, g_xh);
    cudaGetSymbolAddress(&winh, g_winh);
    cudaGetSymbolAddress(&woh, g_woh);
    cudaGetSymbolAddress(&qkvh, g_qkvh);
    cudaGetSymbolAddress(&ah, g_ah);

    const int gemm_smem = 2 * GSTG;                   // 73728
    const int attn_smem = QSTG + 4 * ATBF;            // 55296
    cudaFuncSetAttribute(gemm_f16<0>,
        cudaFuncAttributeMaxDynamicSharedMemorySize, gemm_smem);
    cudaFuncSetAttribute(gemm_f16<2>,
        cudaFuncAttributeMaxDynamicSharedMemorySize, gemm_smem);
    cudaFuncSetAttribute(attn_f16,
        cudaFuncAttributeMaxDynamicSharedMemorySize, attn_smem);

    int n8 = MROWS * EMBED / 8;
    conv_f16<<<(n8 + 255) / 256, 256>>>(x, (__half*)xh, n8);
    n8 = QKV_N * EMBED / 8;
    conv_f16<<<(n8 + 255) / 256, 256>>>(w_in, (__half*)winh, n8);
    n8 = EMBED * EMBED / 8;
    conv_f16<<<(n8 + 255) / 256, 256>>>(w_out, (__half*)woh, n8);

    // 1) QKV projection -> fp16 qkv
    gemm_f16<2><<<dim3(QKV_N / 128, MROWS / 128), 128, gemm_smem>>>(
        (const __half*)xh, (const __half*)winh, b_in,
        nullptr, (__half*)qkvh, QKV_N, EMBED);

    // 2) attention -> fp16
    attn_f16<<<dim3(TLEN / 128, BSZ * NHEAD), 128, attn_smem>>>(
        (const __half*)qkvh, (__half*)ah);

    // 3) output projection -> fp32 out
    gemm_f16<0><<<dim3(EMBED / 128, MROWS / 128), 128, gemm_smem>>>(
        (const __half*)ah, (const __half*)woh, b_out,
        out, nullptr, EMBED, EMBED);
}